// round 12
// baseline (speedup 1.0000x reference)
#include <cuda_runtime.h>
#include <cuda_bf16.h>
#include <math.h>
#include <stdint.h>

#define BB   8
#define LL   2048
#define DD   256
#define DIN_ 512
#define NN   64
#define PP   64
#define HH   8
#define ROWS (BB*LL)          // 16384
#define XPROJ (HH + 2*NN)     // 136
#define NCH  32
#define CT   64

typedef unsigned long long u64;

// ---------------- scratch (device globals) ---------------------------------
__device__ __nv_bfloat16 g_xh[ROWS*DD],   g_xl[ROWS*DD];
__device__ float         g_ur [ROWS*DIN_];
__device__ __nv_bfloat16 g_uh[ROWS*DIN_], g_ul[ROWS*DIN_];
__device__ float         g_dbc[ROWS*XPROJ];
__device__ float         g_yc [ROWS*DIN_];
__device__ __nv_bfloat16 g_yh[ROWS*DIN_], g_yl[ROWS*DIN_];
__device__ float         g_S  [BB*HH*NCH*NN*PP];
__device__ float         g_hin[BB*HH*NCH*NN*PP];
__device__ float         g_la [BB*HH*NCH*CT];
__device__ float         g_pa [BB*HH*NCH];
__device__ __nv_bfloat16 g_w1h[DIN_*DD],    g_w1l[DIN_*DD];
__device__ __nv_bfloat16 g_w2h[XPROJ*DIN_], g_w2l[XPROJ*DIN_];
__device__ __nv_bfloat16 g_w3h[DD*DIN_],    g_w3l[DD*DIN_];

// ---------------- helpers ---------------------------------------------------
__device__ __forceinline__ uint32_t smem_u32(const void* p){
    uint32_t a;
    asm("{ .reg .u64 t; cvta.to.shared.u64 t, %1; cvt.u32.u64 %0, t; }" : "=r"(a) : "l"(p));
    return a;
}
__device__ __forceinline__ void cp16(uint32_t dst, const void* src, int sz){
    asm volatile("cp.async.ca.shared.global [%0], [%1], 16, %2;"
                 :: "r"(dst), "l"(src), "r"(sz) : "memory");
}
#define CP_COMMIT() asm volatile("cp.async.commit_group;" ::: "memory")
#define CP_WAIT2()  asm volatile("cp.async.wait_group 2;" ::: "memory")

#define LDSM4(r, a) asm volatile( \
    "ldmatrix.sync.aligned.m8n8.x4.shared.b16 {%0,%1,%2,%3}, [%4];" \
    : "=r"((r)[0]),"=r"((r)[1]),"=r"((r)[2]),"=r"((r)[3]) : "r"(a))

__device__ __forceinline__ void mma_bf16(float* d, const uint32_t* a, const uint32_t* b){
    asm volatile("mma.sync.aligned.m16n8k16.row.col.f32.bf16.bf16.f32 "
        "{%0,%1,%2,%3}, {%4,%5,%6,%7}, {%8,%9}, {%0,%1,%2,%3};"
        : "+f"(d[0]), "+f"(d[1]), "+f"(d[2]), "+f"(d[3])
        : "r"(a[0]), "r"(a[1]), "r"(a[2]), "r"(a[3]), "r"(b[0]), "r"(b[1]));
}

// packed f32x2
#define PK2(d, lo, hi) asm("mov.b64 %0, {%1,%2};" : "=l"(d) : "r"(__float_as_uint(lo)), "r"(__float_as_uint(hi)))
#define DUP2(d, x)     asm("mov.b64 %0, {%1,%1};" : "=l"(d) : "r"(__float_as_uint(x)))
#define UPK2(lo, hi, v) do { uint32_t _a,_b; asm("mov.b64 {%0,%1}, %2;" : "=r"(_a), "=r"(_b) : "l"(v)); lo=__uint_as_float(_a); hi=__uint_as_float(_b); } while(0)
#define F2ACC(d, a, b) asm("fma.rn.f32x2 %0, %1, %2, %0;" : "+l"(d) : "l"(a), "l"(b))

// reconstruct 4 floats from hi/lo bf16 quads
__device__ __forceinline__ float4 ld4hl(const __nv_bfloat16* hp, const __nv_bfloat16* lp){
    uint2 vh = *(const uint2*)hp;
    uint2 vl = *(const uint2*)lp;
    __nv_bfloat162 h0 = *(__nv_bfloat162*)&vh.x, h1 = *(__nv_bfloat162*)&vh.y;
    __nv_bfloat162 l0 = *(__nv_bfloat162*)&vl.x, l1 = *(__nv_bfloat162*)&vl.y;
    float4 r;
    r.x = __bfloat162float(h0.x) + __bfloat162float(l0.x);
    r.y = __bfloat162float(h0.y) + __bfloat162float(l0.y);
    r.z = __bfloat162float(h1.x) + __bfloat162float(l1.x);
    r.w = __bfloat162float(h1.y) + __bfloat162float(l1.y);
    return r;
}

// ---------------- weight prep ------------------------------------------------
__global__ __launch_bounds__(256) void wprep(const float* __restrict__ W,
        __nv_bfloat16* __restrict__ oh, __nv_bfloat16* __restrict__ ol, int K, int N)
{
    int idx = blockIdx.x * 256 + threadIdx.x;
    if (idx >= K * N) return;
    int n = idx / K, k = idx - n * K;
    float v = W[(size_t)k * N + n];
    __nv_bfloat16 hh = __float2bfloat16(v);
    oh[idx] = hh;
    ol[idx] = __float2bfloat16(v - __bfloat162float(hh));
}

// ---------------- LayerNorm -> bf16 hi/lo ----------------------------------
template<int W>
__global__ __launch_bounds__(256) void ln_bf(const float* __restrict__ x,
        const float* __restrict__ w, const float* __restrict__ b,
        __nv_bfloat16* __restrict__ yh, __nv_bfloat16* __restrict__ yl)
{
    constexpr int E = W / 256;
    int row = blockIdx.x;
    const float* xr = x + (size_t)row * W;
    float v[E]; float s = 0.f, q = 0.f;
#pragma unroll
    for (int i = 0; i < E; i++) { v[i] = xr[threadIdx.x + 256*i]; s += v[i]; q += v[i]*v[i]; }
#pragma unroll
    for (int o = 16; o; o >>= 1) {
        s += __shfl_xor_sync(0xffffffffu, s, o);
        q += __shfl_xor_sync(0xffffffffu, q, o);
    }
    __shared__ float rs[8], rq[8];
    if ((threadIdx.x & 31) == 0) { rs[threadIdx.x>>5] = s; rq[threadIdx.x>>5] = q; }
    __syncthreads();
    float S = 0.f, Q = 0.f;
#pragma unroll
    for (int i = 0; i < 8; i++) { S += rs[i]; Q += rq[i]; }
    float mean = S / (float)W;
    float rstd = rsqrtf(Q / (float)W - mean*mean + 1e-5f);
#pragma unroll
    for (int i = 0; i < E; i++) {
        int c = threadIdx.x + 256*i;
        float o = (v[i] - mean) * rstd * w[c] + b[c];
        __nv_bfloat16 hh = __float2bfloat16(o);
        yh[(size_t)row*W + c] = hh;
        yl[(size_t)row*W + c] = __float2bfloat16(o - __bfloat162float(hh));
    }
}

// ---------------- HMMA bf16-split GEMM, 3-stage cp.async pipeline -----------
#define HMAT   10240            // 128 rows x 80B per matrix
#define HSTAGE 40960            // 4 matrices
#define HSMEM  122880           // 3 stages
__global__ __launch_bounds__(256) void hgemm(
    const __nv_bfloat16* __restrict__ Ah, const __nv_bfloat16* __restrict__ Al,
    const __nv_bfloat16* __restrict__ Bh, const __nv_bfloat16* __restrict__ Bl,
    float* __restrict__ C, const float* __restrict__ addend,
    int M, int N, int K)
{
    extern __shared__ char hsm[];
    const uint32_t sb = smem_u32(hsm);
    const int tid = threadIdx.x, wid = tid >> 5, lane = tid & 31;
    const int m0 = blockIdx.x * 128, n0 = blockIdx.y * 128;
    const int wm = (wid >> 1) * 32, wn = (wid & 1) * 64;
    const int NC = K >> 5;

    float acc[2][8][4];
#pragma unroll
    for (int i = 0; i < 2; i++)
#pragma unroll
        for (int j = 0; j < 8; j++)
#pragma unroll
            for (int q = 0; q < 4; q++) acc[i][j][q] = 0.f;

    auto issue = [&](int c){
        int s = c % 3;
        int k0 = c << 5;
#pragma unroll
        for (int i = 0; i < 8; i++) {
            int idx = tid + i * 256;
            int mat = idx >> 9, w = idx & 511, row = w >> 2, cc = w & 3;
            uint32_t dst = sb + s*HSTAGE + mat*HMAT + row*80 + cc*16;
            if (mat == 0)
                cp16(dst, Ah + (size_t)(m0 + row) * K + k0 + cc*8, 16);
            else if (mat == 1)
                cp16(dst, Al + (size_t)(m0 + row) * K + k0 + cc*8, 16);
            else {
                int n = n0 + row;
                int ok = (n < N);
                const __nv_bfloat16* Bp = (mat == 2) ? Bh : Bl;
                cp16(dst, Bp + (size_t)(ok ? n : 0) * K + k0 + cc*8, ok ? 16 : 0);
            }
        }
    };

    const int rA  = wm + (lane & 15);
    const int kAo = (lane >> 4) * 16;
    const int rB  = wn + (lane & 7) + ((lane >> 4) & 1) * 8;
    const int kBo = ((lane >> 3) & 1) * 16;

    issue(0); CP_COMMIT();
    if (NC > 1) issue(1);
    CP_COMMIT();

    for (int c = 0; c < NC; c++) {
        if (c + 2 < NC) issue(c + 2);
        CP_COMMIT();
        CP_WAIT2();
        __syncthreads();
        uint32_t st = sb + (c % 3) * HSTAGE;
#pragma unroll
        for (int ks = 0; ks < 2; ks++) {
            int ksb = ks * 32;
            uint32_t ah[2][4], al[2][4];
            uint32_t aAdr = st + rA*80 + ksb + kAo;
            LDSM4(ah[0], aAdr);
            LDSM4(ah[1], aAdr + 16*80);
            LDSM4(al[0], aAdr + HMAT);
            LDSM4(al[1], aAdr + HMAT + 16*80);
            uint32_t bh[8][2], bl[8][2];
#pragma unroll
            for (int jp = 0; jp < 4; jp++) {
                uint32_t r4[4];
                uint32_t bAdr = st + 2*HMAT + (rB + jp*16)*80 + ksb + kBo;
                LDSM4(r4, bAdr);
                bh[jp*2  ][0]=r4[0]; bh[jp*2  ][1]=r4[1];
                bh[jp*2+1][0]=r4[2]; bh[jp*2+1][1]=r4[3];
                LDSM4(r4, bAdr + HMAT);
                bl[jp*2  ][0]=r4[0]; bl[jp*2  ][1]=r4[1];
                bl[jp*2+1][0]=r4[2]; bl[jp*2+1][1]=r4[3];
            }
#pragma unroll
            for (int i = 0; i < 2; i++)
#pragma unroll
                for (int j = 0; j < 8; j++) {
                    mma_bf16(acc[i][j], ah[i], bh[j]);
                    mma_bf16(acc[i][j], ah[i], bl[j]);
                    mma_bf16(acc[i][j], al[i], bh[j]);
                }
        }
        __syncthreads();
    }

    const int g = lane >> 2, tg = lane & 3;
#pragma unroll
    for (int i = 0; i < 2; i++) {
#pragma unroll
        for (int j = 0; j < 8; j++) {
            int col = n0 + wn + j*8 + tg*2;
            if (col >= N) continue;
            int mA = m0 + wm + i*16 + g;
            int mB = mA + 8;
            float2 v0 = make_float2(acc[i][j][0], acc[i][j][1]);
            float2 v1 = make_float2(acc[i][j][2], acc[i][j][3]);
            if (addend) {
                float2 a0 = *(const float2*)(addend + (size_t)mA * N + col);
                float2 a1 = *(const float2*)(addend + (size_t)mB * N + col);
                v0.x += a0.x; v0.y += a0.y; v1.x += a1.x; v1.y += a1.y;
            }
            *(float2*)(C + (size_t)mA * N + col) = v0;
            *(float2*)(C + (size_t)mB * N + col) = v1;
        }
    }
}

// ---------------- skinny GEMM: dbc cols 128..135 ----------------------------
__global__ __launch_bounds__(256) void skinny8(const float* __restrict__ Wx)
{
    __shared__ float sW[512*9];
    const int tid = threadIdx.x;
#pragma unroll
    for (int t = 0; t < 16; t++) {
        int idx = tid + t * 256;
        int k = idx >> 3, c = idx & 7;
        sW[k*9 + c] = Wx[(size_t)k * XPROJ + 128 + c];
    }
    __syncthreads();
    int row = blockIdx.x * 8 + (tid >> 5);
    int lane = tid & 31;
    float acc[8];
#pragma unroll
    for (int c = 0; c < 8; c++) acc[c] = 0.f;
    const __nv_bfloat16* uh = g_uh + (size_t)row * DIN_;
    const __nv_bfloat16* ul = g_ul + (size_t)row * DIN_;
#pragma unroll
    for (int i = 0; i < 4; i++) {
        int k = (lane + i * 32) * 4;
        float4 uv = ld4hl(uh + k, ul + k);
        float u4[4] = {uv.x, uv.y, uv.z, uv.w};
#pragma unroll
        for (int q = 0; q < 4; q++)
#pragma unroll
            for (int c = 0; c < 8; c++)
                acc[c] = fmaf(u4[q], sW[(k+q)*9 + c], acc[c]);
    }
#pragma unroll
    for (int o = 16; o; o >>= 1)
#pragma unroll
        for (int c = 0; c < 8; c++)
            acc[c] += __shfl_xor_sync(0xffffffffu, acc[c], o);
    if (lane == 0) {
#pragma unroll
        for (int c = 0; c < 8; c++)
            g_dbc[(size_t)row * XPROJ + 128 + c] = acc[c];
    }
}

// ---------------- depthwise conv3 + GELU -> bf16 hi/lo (x4 vectorized) ------
__global__ __launch_bounds__(256) void convgelu_k(const float* __restrict__ cw,
                                                  const float* __restrict__ cb)
{
    int idx = blockIdx.x * 256 + threadIdx.x;       // over ROWS*DIN_/4
    if (idx >= ROWS * DIN_ / 4) return;
    int cg = idx & 127;                             // channel group
    int l  = (idx >> 7) & (LL - 1);
    float4 mid = *(const float4*)(g_ur + (size_t)idx*4);
    float4 lft = make_float4(0,0,0,0), rgt = make_float4(0,0,0,0);
    if (l > 0)      lft = *(const float4*)(g_ur + (size_t)(idx - 128)*4);
    if (l < LL - 1) rgt = *(const float4*)(g_ur + (size_t)(idx + 128)*4);
    float m[4] = {mid.x, mid.y, mid.z, mid.w};
    float a[4] = {lft.x, lft.y, lft.z, lft.w};
    float r[4] = {rgt.x, rgt.y, rgt.z, rgt.w};
    __nv_bfloat16 oh[4], ol[4];
#pragma unroll
    for (int q = 0; q < 4; q++) {
        int c = cg * 4 + q;
        float x = a[q]*cw[c*3] + m[q]*cw[c*3+1] + r[q]*cw[c*3+2] + cb[c];
        float g = 0.5f * x * (1.f + erff(x * 0.7071067811865476f));
        oh[q] = __float2bfloat16(g);
        ol[q] = __float2bfloat16(g - __bfloat162float(oh[q]));
    }
    *(uint2*)(g_uh + (size_t)idx*4) = *(uint2*)oh;
    *(uint2*)(g_ul + (size_t)idx*4) = *(uint2*)ol;
}

// ---------------- SSD phase A ------------------------------------------------
__global__ __launch_bounds__(256,2) void ssdA(const float* __restrict__ dt_bias,
                                              const float* __restrict__ A_log)
{
    extern __shared__ float sm[];
    float* sB  = sm;            // 64 x 65
    float* sC  = sm + 4160;
    float* sX  = sm + 8320;
    float* sP  = sm + 12480;
    float* sdt = sm + 16640;
    float* sla = sdt + 64;
    float* sw  = sla + 64;
    const int c = blockIdx.x, h = blockIdx.y, b = blockIdx.z;
    const int tid = threadIdx.x;
    const int tx = tid & 15, ty = tid >> 4;
    const size_t r0 = (size_t)b * LL + c * CT;
    const int bh = b * HH + h;

#pragma unroll
    for (int i = 0; i < 4; i++) {
        int row = i * 16 + ty;
        const float* dr = g_dbc + (r0 + row) * XPROJ;
        float4 bv = *(const float4*)(dr + 8  + tx*4);
        float4 cv = *(const float4*)(dr + 72 + tx*4);
        size_t uoff = (r0 + row)*DIN_ + h*64 + tx*4;
        float4 xv = ld4hl(g_uh + uoff, g_ul + uoff);
        sB[row*65 + tx*4+0]=bv.x; sB[row*65 + tx*4+1]=bv.y;
        sB[row*65 + tx*4+2]=bv.z; sB[row*65 + tx*4+3]=bv.w;
        sC[row*65 + tx*4+0]=cv.x; sC[row*65 + tx*4+1]=cv.y;
        sC[row*65 + tx*4+2]=cv.z; sC[row*65 + tx*4+3]=cv.w;
        sX[row*65 + tx*4+0]=xv.x; sX[row*65 + tx*4+1]=xv.y;
        sX[row*65 + tx*4+2]=xv.z; sX[row*65 + tx*4+3]=xv.w;
    }
    if (tid < 64) {
        float xx = g_dbc[(r0 + tid)*XPROJ + h] + dt_bias[h];
        float dt = (xx > 20.f) ? xx : log1pf(expf(xx));
        float la = -dt * expf(A_log[h]);
        int lane = tid & 31;
        float v = la;
#pragma unroll
        for (int o = 1; o < 32; o <<= 1) {
            float pv = __shfl_up_sync(0xffffffffu, v, o);
            if (lane >= o) v += pv;
        }
        sdt[tid] = dt;
        sla[tid] = v;
    }
    __syncthreads();
    if (tid >= 32 && tid < 64) sla[tid] += sla[31];
    __syncthreads();
    if (tid < 64) sw[tid] = sdt[tid] * __expf(sla[63] - sla[tid]);
    __syncthreads();

    u64 acc2[4][2];
#pragma unroll
    for (int i=0;i<4;i++) { acc2[i][0]=0ull; acc2[i][1]=0ull; }
#pragma unroll 8
    for (int n = 0; n < 64; n++) {
        u64 a2[4], b2[2];
#pragma unroll
        for (int i=0;i<4;i++) DUP2(a2[i], sC[(ty*4+i)*65 + n]);
        PK2(b2[0], sB[(tx*4+0)*65 + n], sB[(tx*4+1)*65 + n]);
        PK2(b2[1], sB[(tx*4+2)*65 + n], sB[(tx*4+3)*65 + n]);
#pragma unroll
        for (int i=0;i<4;i++) {
            F2ACC(acc2[i][0], a2[i], b2[0]);
            F2ACC(acc2[i][1], a2[i], b2[1]);
        }
    }
#pragma unroll
    for (int i=0;i<4;i++) {
        int t = ty*4 + i;
        float pv[4];
        UPK2(pv[0], pv[1], acc2[i][0]);
        UPK2(pv[2], pv[3], acc2[i][1]);
#pragma unroll
        for (int j=0;j<4;j++) {
            int s = tx*4 + j;
            sP[t*65 + s] = (s <= t) ? pv[j] * __expf(sla[t] - sla[s]) * sdt[s] : 0.f;
        }
    }
    __syncthreads();

#pragma unroll
    for (int i=0;i<4;i++) { acc2[i][0]=0ull; acc2[i][1]=0ull; }
#pragma unroll 8
    for (int s = 0; s < 64; s++) {
        u64 a2[4], b2[2];
#pragma unroll
        for (int i=0;i<4;i++) DUP2(a2[i], sP[(ty*4+i)*65 + s]);
        PK2(b2[0], sX[s*65 + tx*4+0], sX[s*65 + tx*4+1]);
        PK2(b2[1], sX[s*65 + tx*4+2], sX[s*65 + tx*4+3]);
#pragma unroll
        for (int i=0;i<4;i++) {
            F2ACC(acc2[i][0], a2[i], b2[0]);
            F2ACC(acc2[i][1], a2[i], b2[1]);
        }
    }
#pragma unroll
    for (int i=0;i<4;i++) {
        int t = ty*4 + i;
        float4 y;
        UPK2(y.x, y.y, acc2[i][0]);
        UPK2(y.z, y.w, acc2[i][1]);
        *(float4*)(g_yc + (r0 + t)*DIN_ + h*64 + tx*4) = y;
    }
    __syncthreads();

#pragma unroll
    for (int i = 0; i < 4; i++) {
        int row = i * 16 + ty;
        float wv = sw[row];
#pragma unroll
        for (int j = 0; j < 4; j++)
            sP[row*65 + tx*4 + j] = wv * sX[row*65 + tx*4 + j];
    }
    __syncthreads();

#pragma unroll
    for (int i=0;i<4;i++) { acc2[i][0]=0ull; acc2[i][1]=0ull; }
#pragma unroll 8
    for (int s = 0; s < 64; s++) {
        u64 a2[4], b2[2];
#pragma unroll
        for (int i=0;i<4;i++) DUP2(a2[i], sB[s*65 + ty*4 + i]);
        PK2(b2[0], sP[s*65 + tx*4+0], sP[s*65 + tx*4+1]);
        PK2(b2[1], sP[s*65 + tx*4+2], sP[s*65 + tx*4+3]);
#pragma unroll
        for (int i=0;i<4;i++) {
            F2ACC(acc2[i][0], a2[i], b2[0]);
            F2ACC(acc2[i][1], a2[i], b2[1]);
        }
    }
    size_t so = ((size_t)bh * NCH + c) * (NN*PP);
#pragma unroll
    for (int i=0;i<4;i++) {
        int n = ty*4 + i;
        float4 v;
        UPK2(v.x, v.y, acc2[i][0]);
        UPK2(v.z, v.w, acc2[i][1]);
        *(float4*)(g_S + so + n*64 + tx*4) = v;
    }
    if (tid < 64) g_la[((size_t)bh*NCH + c)*CT + tid] = sla[tid];
    if (tid == 0) g_pa[bh*NCH + c] = __expf(sla[63]);
}

// ---------------- SSD phase B ------------------------------------------------
__global__ __launch_bounds__(256) void ssdB()
{
    int bh = blockIdx.x, tid = threadIdx.x;
    float h[16];
#pragma unroll
    for (int i=0;i<16;i++) h[i]=0.f;
    size_t base = (size_t)bh * NCH * (NN*PP);
    for (int c = 0; c < NCH; c++) {
        float pa = g_pa[bh*NCH + c];
        size_t cb = base + (size_t)c * (NN*PP);
#pragma unroll
        for (int i=0;i<16;i++) {
            size_t idx = cb + i*256 + tid;
            g_hin[idx] = h[i];
            h[i] = h[i]*pa + g_S[idx];
        }
    }
}

// ---------------- SSD phase C ------------------------------------------------
__global__ __launch_bounds__(256,2) void ssdC(const float* __restrict__ Ds)
{
    __shared__ float sCl[64*65];
    __shared__ float sH [64*65];
    __shared__ float sla2[64];
    const int c = blockIdx.x, h = blockIdx.y, b = blockIdx.z;
    const int tid = threadIdx.x;
    const int tx = tid & 15, ty = tid >> 4;
    const size_t r0 = (size_t)b * LL + c * CT;
    const int bh = b * HH + h;

    if (tid < 64) sla2[tid] = g_la[((size_t)bh*NCH + c)*CT + tid];
    __syncthreads();
#pragma unroll
    for (int i = 0; i < 4; i++) {
        int row = i * 16 + ty;
        float4 cv = *(const float4*)(g_dbc + (r0 + row)*XPROJ + 72 + tx*4);
        float e = __expf(sla2[row]);
        float4 hv = *(const float4*)(g_hin + ((size_t)bh*NCH + c)*(NN*PP) + row*64 + tx*4);
        sCl[row*65 + tx*4+0] = cv.x*e; sCl[row*65 + tx*4+1] = cv.y*e;
        sCl[row*65 + tx*4+2] = cv.z*e; sCl[row*65 + tx*4+3] = cv.w*e;
        sH [row*65 + tx*4+0] = hv.x;   sH [row*65 + tx*4+1] = hv.y;
        sH [row*65 + tx*4+2] = hv.z;   sH [row*65 + tx*4+3] = hv.w;
    }
    __syncthreads();

    u64 acc2[4][2];
#pragma unroll
    for (int i=0;i<4;i++) { acc2[i][0]=0ull; acc2[i][1]=0ull; }
#pragma unroll 8
    for (int n = 0; n < 64; n++) {
        u64 a2[4], b2[2];
#pragma unroll
        for (int i=0;i<4;i++) DUP2(a2[i], sCl[(ty*4+i)*65 + n]);
        PK2(b2[0], sH[n*65 + tx*4+0], sH[n*65 + tx*4+1]);
        PK2(b2[1], sH[n*65 + tx*4+2], sH[n*65 + tx*4+3]);
#pragma unroll
        for (int i=0;i<4;i++) {
            F2ACC(acc2[i][0], a2[i], b2[0]);
            F2ACC(acc2[i][1], a2[i], b2[1]);
        }
    }
    float dsh = Ds[h];
#pragma unroll
    for (int i=0;i<4;i++) {
        int t = ty*4 + i;
        float* yp = g_yc + (r0 + t)*DIN_ + h*64 + tx*4;
        float4 y1 = *(float4*)yp;
        size_t uoff = (r0 + t)*DIN_ + h*64 + tx*4;
        float4 xv = ld4hl(g_uh + uoff, g_ul + uoff);
        float a0,a1,a2v,a3;
        UPK2(a0, a1, acc2[i][0]);
        UPK2(a2v, a3, acc2[i][1]);
        y1.x += a0 + dsh*xv.x;
        y1.y += a1 + dsh*xv.y;
        y1.z += a2v + dsh*xv.z;
        y1.w += a3 + dsh*xv.w;
        *(float4*)yp = y1;
    }
}

// ---------------- launch ----------------------------------------------------
extern "C" void kernel_launch(void* const* d_in, const int* in_sizes, int n_in,
                              void* d_out, int out_size)
{
    const float* src     = (const float*)d_in[0];
    const float* ln_w    = (const float*)d_in[1];
    const float* ln_b    = (const float*)d_in[2];
    const float* W_in    = (const float*)d_in[3];
    const float* conv_w  = (const float*)d_in[4];
    const float* conv_b  = (const float*)d_in[5];
    const float* W_xproj = (const float*)d_in[6];
    const float* dt_bias = (const float*)d_in[7];
    const float* A_log   = (const float*)d_in[8];
    const float* Ds      = (const float*)d_in[9];
    const float* oln_w   = (const float*)d_in[10];
    const float* oln_b   = (const float*)d_in[11];
    const float* W_out   = (const float*)d_in[12];
    float* out = (float*)d_out;

    __nv_bfloat16 *p_xh,*p_xl,*p_uh,*p_ul,*p_yh,*p_yl;
    __nv_bfloat16 *p_w1h,*p_w1l,*p_w2h,*p_w2l,*p_w3h,*p_w3l;
    float *p_ur,*p_dbc,*p_yc;
    cudaGetSymbolAddress((void**)&p_xh, g_xh);   cudaGetSymbolAddress((void**)&p_xl, g_xl);
    cudaGetSymbolAddress((void**)&p_uh, g_uh);   cudaGetSymbolAddress((void**)&p_ul, g_ul);
    cudaGetSymbolAddress((void**)&p_yh, g_yh);   cudaGetSymbolAddress((void**)&p_yl, g_yl);
    cudaGetSymbolAddress((void**)&p_w1h, g_w1h); cudaGetSymbolAddress((void**)&p_w1l, g_w1l);
    cudaGetSymbolAddress((void**)&p_w2h, g_w2h); cudaGetSymbolAddress((void**)&p_w2l, g_w2l);
    cudaGetSymbolAddress((void**)&p_w3h, g_w3h); cudaGetSymbolAddress((void**)&p_w3l, g_w3l);
    cudaGetSymbolAddress((void**)&p_ur, g_ur);
    cudaGetSymbolAddress((void**)&p_dbc, g_dbc);
    cudaGetSymbolAddress((void**)&p_yc, g_yc);

    const int ASMEM = 67328;
    cudaFuncSetAttribute(ssdA, cudaFuncAttributeMaxDynamicSharedMemorySize, ASMEM);
    cudaFuncSetAttribute(hgemm, cudaFuncAttributeMaxDynamicSharedMemorySize, HSMEM);

    wprep<<<(DD*DIN_ + 255)/256, 256>>>(W_in,    p_w1h, p_w1l, DD,   DIN_);
    wprep<<<(DIN_*XPROJ + 255)/256, 256>>>(W_xproj, p_w2h, p_w2l, DIN_, XPROJ);
    wprep<<<(DIN_*DD + 255)/256, 256>>>(W_out,   p_w3h, p_w3l, DIN_, DD);

    // 1) LN1 -> bf16 hi/lo
    ln_bf<DD><<<ROWS, 256>>>(src, ln_w, ln_b, p_xh, p_xl);
    // 2) ur = x @ W_in
    hgemm<<<dim3(ROWS/128, 4), 256, HSMEM>>>(p_xh, p_xl, p_w1h, p_w1l, p_ur, nullptr,
                                             ROWS, DIN_, DD);
    // 3) u = gelu(conv3(ur)+b) -> bf16 hi/lo only
    convgelu_k<<<(ROWS*DIN_/4 + 255)/256, 256>>>(conv_w, conv_b);
    // 4) dbc = u @ W_xproj
    hgemm<<<dim3(ROWS/128, 1), 256, HSMEM>>>(p_uh, p_ul, p_w2h, p_w2l, p_dbc, nullptr,
                                             ROWS, XPROJ, DIN_);
    skinny8<<<ROWS/8, 256>>>(W_xproj);
    // 5) chunked scan
    ssdA<<<dim3(NCH, HH, BB), 256, ASMEM>>>(dt_bias, A_log);
    ssdB<<<BB*HH, 256>>>();
    ssdC<<<dim3(NCH, HH, BB), 256>>>(Ds);
    // 6) oln -> bf16 hi/lo
    ln_bf<DIN_><<<ROWS, 256>>>(p_yc, oln_w, oln_b, p_yh, p_yl);
    // 7) out = src + yln @ W_out
    hgemm<<<dim3(ROWS/128, 2), 256, HSMEM>>>(p_yh, p_yl, p_w3h, p_w3l, out, src,
                                             ROWS, DD, DIN_);
}

// round 13
// speedup vs baseline: 1.0193x; 1.0193x over previous
#include <cuda_runtime.h>
#include <cuda_bf16.h>
#include <math.h>
#include <stdint.h>

#define BB   8
#define LL   2048
#define DD   256
#define DIN_ 512
#define NN   64
#define PP   64
#define HH   8
#define ROWS (BB*LL)          // 16384
#define XPROJ (HH + 2*NN)     // 136
#define NCH  32
#define CT   64

typedef unsigned long long u64;

// ---------------- scratch (device globals) ---------------------------------
__device__ __nv_bfloat16 g_xh[ROWS*DD],   g_xl[ROWS*DD];
__device__ float         g_ur [ROWS*DIN_];
__device__ __nv_bfloat16 g_uh[ROWS*DIN_], g_ul[ROWS*DIN_];
__device__ float         g_dbc[ROWS*XPROJ];
__device__ float         g_yc [ROWS*DIN_];
__device__ __nv_bfloat16 g_yh[ROWS*DIN_], g_yl[ROWS*DIN_];
__device__ float         g_S  [BB*HH*NCH*NN*PP];
__device__ float         g_hin[BB*HH*NCH*NN*PP];
__device__ float         g_la [BB*HH*NCH*CT];
__device__ float         g_pa [BB*HH*NCH];
__device__ __nv_bfloat16 g_w1h[DIN_*DD],    g_w1l[DIN_*DD];
__device__ __nv_bfloat16 g_w2h[XPROJ*DIN_], g_w2l[XPROJ*DIN_];
__device__ __nv_bfloat16 g_w3h[DD*DIN_],    g_w3l[DD*DIN_];

// ---------------- helpers ---------------------------------------------------
__device__ __forceinline__ uint32_t smem_u32(const void* p){
    uint32_t a;
    asm("{ .reg .u64 t; cvta.to.shared.u64 t, %1; cvt.u32.u64 %0, t; }" : "=r"(a) : "l"(p));
    return a;
}
__device__ __forceinline__ void cp16(uint32_t dst, const void* src, int sz){
    asm volatile("cp.async.ca.shared.global [%0], [%1], 16, %2;"
                 :: "r"(dst), "l"(src), "r"(sz) : "memory");
}
#define CP_COMMIT() asm volatile("cp.async.commit_group;" ::: "memory")
#define CP_WAIT1()  asm volatile("cp.async.wait_group 1;" ::: "memory")
#define CP_WAIT0()  asm volatile("cp.async.wait_group 0;" ::: "memory")

#define LDSM4(r, a) asm volatile( \
    "ldmatrix.sync.aligned.m8n8.x4.shared.b16 {%0,%1,%2,%3}, [%4];" \
    : "=r"((r)[0]),"=r"((r)[1]),"=r"((r)[2]),"=r"((r)[3]) : "r"(a))

__device__ __forceinline__ void mma_bf16(float* d, const uint32_t* a, const uint32_t* b){
    asm volatile("mma.sync.aligned.m16n8k16.row.col.f32.bf16.bf16.f32 "
        "{%0,%1,%2,%3}, {%4,%5,%6,%7}, {%8,%9}, {%0,%1,%2,%3};"
        : "+f"(d[0]), "+f"(d[1]), "+f"(d[2]), "+f"(d[3])
        : "r"(a[0]), "r"(a[1]), "r"(a[2]), "r"(a[3]), "r"(b[0]), "r"(b[1]));
}

// packed f32x2
#define PK2(d, lo, hi) asm("mov.b64 %0, {%1,%2};" : "=l"(d) : "r"(__float_as_uint(lo)), "r"(__float_as_uint(hi)))
#define DUP2(d, x)     asm("mov.b64 %0, {%1,%1};" : "=l"(d) : "r"(__float_as_uint(x)))
#define UPK2(lo, hi, v) do { uint32_t _a,_b; asm("mov.b64 {%0,%1}, %2;" : "=r"(_a), "=r"(_b) : "l"(v)); lo=__uint_as_float(_a); hi=__uint_as_float(_b); } while(0)
#define F2ACC(d, a, b) asm("fma.rn.f32x2 %0, %1, %2, %0;" : "+l"(d) : "l"(a), "l"(b))

__device__ __forceinline__ float4 ld4hl(const __nv_bfloat16* hp, const __nv_bfloat16* lp){
    uint2 vh = *(const uint2*)hp;
    uint2 vl = *(const uint2*)lp;
    __nv_bfloat162 h0 = *(__nv_bfloat162*)&vh.x, h1 = *(__nv_bfloat162*)&vh.y;
    __nv_bfloat162 l0 = *(__nv_bfloat162*)&vl.x, l1 = *(__nv_bfloat162*)&vl.y;
    float4 r;
    r.x = __bfloat162float(h0.x) + __bfloat162float(l0.x);
    r.y = __bfloat162float(h0.y) + __bfloat162float(l0.y);
    r.z = __bfloat162float(h1.x) + __bfloat162float(l1.x);
    r.w = __bfloat162float(h1.y) + __bfloat162float(l1.y);
    return r;
}

// ---------------- weight prep ------------------------------------------------
__global__ __launch_bounds__(256) void wprep(const float* __restrict__ W,
        __nv_bfloat16* __restrict__ oh, __nv_bfloat16* __restrict__ ol, int K, int N)
{
    int idx = blockIdx.x * 256 + threadIdx.x;
    if (idx >= K * N) return;
    int n = idx / K, k = idx - n * K;
    float v = W[(size_t)k * N + n];
    __nv_bfloat16 hh = __float2bfloat16(v);
    oh[idx] = hh;
    ol[idx] = __float2bfloat16(v - __bfloat162float(hh));
}

// ---------------- LayerNorm -> bf16 hi/lo ----------------------------------
template<int W>
__global__ __launch_bounds__(256) void ln_bf(const float* __restrict__ x,
        const float* __restrict__ w, const float* __restrict__ b,
        __nv_bfloat16* __restrict__ yh, __nv_bfloat16* __restrict__ yl)
{
    constexpr int E = W / 256;
    int row = blockIdx.x;
    const float* xr = x + (size_t)row * W;
    float v[E]; float s = 0.f, q = 0.f;
#pragma unroll
    for (int i = 0; i < E; i++) { v[i] = xr[threadIdx.x + 256*i]; s += v[i]; q += v[i]*v[i]; }
#pragma unroll
    for (int o = 16; o; o >>= 1) {
        s += __shfl_xor_sync(0xffffffffu, s, o);
        q += __shfl_xor_sync(0xffffffffu, q, o);
    }
    __shared__ float rs[8], rq[8];
    if ((threadIdx.x & 31) == 0) { rs[threadIdx.x>>5] = s; rq[threadIdx.x>>5] = q; }
    __syncthreads();
    float S = 0.f, Q = 0.f;
#pragma unroll
    for (int i = 0; i < 8; i++) { S += rs[i]; Q += rq[i]; }
    float mean = S / (float)W;
    float rstd = rsqrtf(Q / (float)W - mean*mean + 1e-5f);
#pragma unroll
    for (int i = 0; i < E; i++) {
        int c = threadIdx.x + 256*i;
        float o = (v[i] - mean) * rstd * w[c] + b[c];
        __nv_bfloat16 hh = __float2bfloat16(o);
        yh[(size_t)row*W + c] = hh;
        yl[(size_t)row*W + c] = __float2bfloat16(o - __bfloat162float(hh));
    }
}

// ---------------- HMMA bf16-split GEMM, BM128 x BN64, 2 CTAs/SM -------------
// C = Ah@Bh^T + Ah@Bl^T + Al@Bh^T (+addend). 8 warps, warptile 32x32.
// Stage: Ah(10240) Al(10240) Bh(5120) Bl(5120) = 30720 B; 2 stages = 61440 B.
#define HA_OFF  0
#define HAL_OFF 10240
#define HBH_OFF 20480
#define HBL_OFF 25600
#define HSTG    30720
#define HSMEM   61440
__global__ __launch_bounds__(256,2) void hgemm(
    const __nv_bfloat16* __restrict__ Ah, const __nv_bfloat16* __restrict__ Al,
    const __nv_bfloat16* __restrict__ Bh, const __nv_bfloat16* __restrict__ Bl,
    float* __restrict__ C, const float* __restrict__ addend,
    int M, int N, int K)
{
    extern __shared__ char hsm[];
    const uint32_t sb = smem_u32(hsm);
    const int tid = threadIdx.x, wid = tid >> 5, lane = tid & 31;
    const int m0 = blockIdx.x * 128, n0 = blockIdx.y * 64;
    const int wm = (wid >> 1) * 32, wn = (wid & 1) * 32;
    const int NC = K >> 5;

    float acc[2][4][4];
#pragma unroll
    for (int i = 0; i < 2; i++)
#pragma unroll
        for (int j = 0; j < 4; j++)
#pragma unroll
            for (int q = 0; q < 4; q++) acc[i][j][q] = 0.f;

    auto issue = [&](int c){
        int s = c & 1;
        int k0 = c << 5;
        uint32_t stg = sb + s * HSTG;
#pragma unroll
        for (int i = 0; i < 6; i++) {
            int idx = tid + i * 256;
            if (idx < 1024) {                 // A hi/lo: 512 chunks each
                int mat = idx >> 9, w = idx & 511, row = w >> 2, cc = w & 3;
                uint32_t dst = stg + (mat ? HAL_OFF : HA_OFF) + row*80 + cc*16;
                const __nv_bfloat16* Ap = mat ? Al : Ah;
                cp16(dst, Ap + (size_t)(m0 + row) * K + k0 + cc*8, 16);
            } else {                          // B hi/lo: 256 chunks each
                int j = idx - 1024;
                int mat = j >> 8, w = j & 255, row = w >> 2, cc = w & 3;
                uint32_t dst = stg + (mat ? HBL_OFF : HBH_OFF) + row*80 + cc*16;
                int n = n0 + row;
                int ok = (n < N);
                const __nv_bfloat16* Bp = mat ? Bl : Bh;
                cp16(dst, Bp + (size_t)(ok ? n : 0) * K + k0 + cc*8, ok ? 16 : 0);
            }
        }
    };

    const int rA  = wm + (lane & 15);
    const int kAo = (lane >> 4) * 16;
    const int rB  = wn + (lane & 7) + ((lane >> 4) & 1) * 8;
    const int kBo = ((lane >> 3) & 1) * 16;

    issue(0); CP_COMMIT();

    for (int c = 0; c < NC; c++) {
        int s = c & 1;
        if (c + 1 < NC) { issue(c + 1); CP_COMMIT(); CP_WAIT1(); }
        else            { CP_WAIT0(); }
        __syncthreads();
        uint32_t st = sb + s * HSTG;
#pragma unroll
        for (int ks = 0; ks < 2; ks++) {
            int ksb = ks * 32;
            uint32_t ah[2][4], al[2][4];
            uint32_t aAdr = st + HA_OFF + rA*80 + ksb + kAo;
            LDSM4(ah[0], aAdr);
            LDSM4(ah[1], aAdr + 16*80);
            LDSM4(al[0], aAdr + (HAL_OFF - HA_OFF));
            LDSM4(al[1], aAdr + (HAL_OFF - HA_OFF) + 16*80);
            uint32_t bh[4][2], bl[4][2];
            {
                uint32_t r4[4];
                uint32_t bAdr = st + HBH_OFF + rB*80 + ksb + kBo;
                LDSM4(r4, bAdr);
                bh[0][0]=r4[0]; bh[0][1]=r4[1]; bh[1][0]=r4[2]; bh[1][1]=r4[3];
                LDSM4(r4, bAdr + 16*80);
                bh[2][0]=r4[0]; bh[2][1]=r4[1]; bh[3][0]=r4[2]; bh[3][1]=r4[3];
                LDSM4(r4, bAdr + (HBL_OFF - HBH_OFF));
                bl[0][0]=r4[0]; bl[0][1]=r4[1]; bl[1][0]=r4[2]; bl[1][1]=r4[3];
                LDSM4(r4, bAdr + (HBL_OFF - HBH_OFF) + 16*80);
                bl[2][0]=r4[0]; bl[2][1]=r4[1]; bl[3][0]=r4[2]; bl[3][1]=r4[3];
            }
#pragma unroll
            for (int i = 0; i < 2; i++)
#pragma unroll
                for (int j = 0; j < 4; j++) {
                    mma_bf16(acc[i][j], ah[i], bh[j]);
                    mma_bf16(acc[i][j], ah[i], bl[j]);
                    mma_bf16(acc[i][j], al[i], bh[j]);
                }
        }
        __syncthreads();
    }

    const int g = lane >> 2, tg = lane & 3;
#pragma unroll
    for (int i = 0; i < 2; i++) {
#pragma unroll
        for (int j = 0; j < 4; j++) {
            int col = n0 + wn + j*8 + tg*2;
            if (col >= N) continue;
            int mA = m0 + wm + i*16 + g;
            int mB = mA + 8;
            float2 v0 = make_float2(acc[i][j][0], acc[i][j][1]);
            float2 v1 = make_float2(acc[i][j][2], acc[i][j][3]);
            if (addend) {
                float2 a0 = *(const float2*)(addend + (size_t)mA * N + col);
                float2 a1 = *(const float2*)(addend + (size_t)mB * N + col);
                v0.x += a0.x; v0.y += a0.y; v1.x += a1.x; v1.y += a1.y;
            }
            *(float2*)(C + (size_t)mA * N + col) = v0;
            *(float2*)(C + (size_t)mB * N + col) = v1;
        }
    }
}

// ---------------- skinny GEMM: dbc cols 128..135 ----------------------------
__global__ __launch_bounds__(256) void skinny8(const float* __restrict__ Wx)
{
    __shared__ float sW[512*9];
    const int tid = threadIdx.x;
#pragma unroll
    for (int t = 0; t < 16; t++) {
        int idx = tid + t * 256;
        int k = idx >> 3, c = idx & 7;
        sW[k*9 + c] = Wx[(size_t)k * XPROJ + 128 + c];
    }
    __syncthreads();
    int row = blockIdx.x * 8 + (tid >> 5);
    int lane = tid & 31;
    float acc[8];
#pragma unroll
    for (int c = 0; c < 8; c++) acc[c] = 0.f;
    const __nv_bfloat16* uh = g_uh + (size_t)row * DIN_;
    const __nv_bfloat16* ul = g_ul + (size_t)row * DIN_;
#pragma unroll
    for (int i = 0; i < 4; i++) {
        int k = (lane + i * 32) * 4;
        float4 uv = ld4hl(uh + k, ul + k);
        float u4[4] = {uv.x, uv.y, uv.z, uv.w};
#pragma unroll
        for (int q = 0; q < 4; q++)
#pragma unroll
            for (int c = 0; c < 8; c++)
                acc[c] = fmaf(u4[q], sW[(k+q)*9 + c], acc[c]);
    }
#pragma unroll
    for (int o = 16; o; o >>= 1)
#pragma unroll
        for (int c = 0; c < 8; c++)
            acc[c] += __shfl_xor_sync(0xffffffffu, acc[c], o);
    if (lane == 0) {
#pragma unroll
        for (int c = 0; c < 8; c++)
            g_dbc[(size_t)row * XPROJ + 128 + c] = acc[c];
    }
}

// ---------------- depthwise conv3 + GELU -> bf16 hi/lo ----------------------
__global__ __launch_bounds__(256) void convgelu_k(const float* __restrict__ cw,
                                                  const float* __restrict__ cb)
{
    int idx = blockIdx.x * 256 + threadIdx.x;       // over ROWS*DIN_/4
    if (idx >= ROWS * DIN_ / 4) return;
    int cg = idx & 127;
    int l  = (idx >> 7) & (LL - 1);
    float4 mid = *(const float4*)(g_ur + (size_t)idx*4);
    float4 lft = make_float4(0,0,0,0), rgt = make_float4(0,0,0,0);
    if (l > 0)      lft = *(const float4*)(g_ur + (size_t)(idx - 128)*4);
    if (l < LL - 1) rgt = *(const float4*)(g_ur + (size_t)(idx + 128)*4);
    float m[4] = {mid.x, mid.y, mid.z, mid.w};
    float a[4] = {lft.x, lft.y, lft.z, lft.w};
    float r[4] = {rgt.x, rgt.y, rgt.z, rgt.w};
    __nv_bfloat16 oh[4], ol[4];
#pragma unroll
    for (int q = 0; q < 4; q++) {
        int c = cg * 4 + q;
        float x = a[q]*cw[c*3] + m[q]*cw[c*3+1] + r[q]*cw[c*3+2] + cb[c];
        float g = 0.5f * x * (1.f + erff(x * 0.7071067811865476f));
        oh[q] = __float2bfloat16(g);
        ol[q] = __float2bfloat16(g - __bfloat162float(oh[q]));
    }
    *(uint2*)(g_uh + (size_t)idx*4) = *(uint2*)oh;
    *(uint2*)(g_ul + (size_t)idx*4) = *(uint2*)ol;
}

// ---------------- SSD phase A ------------------------------------------------
__global__ __launch_bounds__(256,2) void ssdA(const float* __restrict__ dt_bias,
                                              const float* __restrict__ A_log)
{
    extern __shared__ float sm[];
    float* sB  = sm;            // 64 x 65
    float* sC  = sm + 4160;
    float* sX  = sm + 8320;
    float* sP  = sm + 12480;
    float* sdt = sm + 16640;
    float* sla = sdt + 64;
    float* sw  = sla + 64;
    const int c = blockIdx.x, h = blockIdx.y, b = blockIdx.z;
    const int tid = threadIdx.x;
    const int tx = tid & 15, ty = tid >> 4;
    const size_t r0 = (size_t)b * LL + c * CT;
    const int bh = b * HH + h;

#pragma unroll
    for (int i = 0; i < 4; i++) {
        int row = i * 16 + ty;
        const float* dr = g_dbc + (r0 + row) * XPROJ;
        float4 bv = *(const float4*)(dr + 8  + tx*4);
        float4 cv = *(const float4*)(dr + 72 + tx*4);
        size_t uoff = (r0 + row)*DIN_ + h*64 + tx*4;
        float4 xv = ld4hl(g_uh + uoff, g_ul + uoff);
        sB[row*65 + tx*4+0]=bv.x; sB[row*65 + tx*4+1]=bv.y;
        sB[row*65 + tx*4+2]=bv.z; sB[row*65 + tx*4+3]=bv.w;
        sC[row*65 + tx*4+0]=cv.x; sC[row*65 + tx*4+1]=cv.y;
        sC[row*65 + tx*4+2]=cv.z; sC[row*65 + tx*4+3]=cv.w;
        sX[row*65 + tx*4+0]=xv.x; sX[row*65 + tx*4+1]=xv.y;
        sX[row*65 + tx*4+2]=xv.z; sX[row*65 + tx*4+3]=xv.w;
    }
    if (tid < 64) {
        float xx = g_dbc[(r0 + tid)*XPROJ + h] + dt_bias[h];
        float dt = (xx > 20.f) ? xx : log1pf(expf(xx));
        float la = -dt * expf(A_log[h]);
        int lane = tid & 31;
        float v = la;
#pragma unroll
        for (int o = 1; o < 32; o <<= 1) {
            float pv = __shfl_up_sync(0xffffffffu, v, o);
            if (lane >= o) v += pv;
        }
        sdt[tid] = dt;
        sla[tid] = v;
    }
    __syncthreads();
    if (tid >= 32 && tid < 64) sla[tid] += sla[31];
    __syncthreads();
    if (tid < 64) sw[tid] = sdt[tid] * __expf(sla[63] - sla[tid]);
    __syncthreads();

    u64 acc2[4][2];
#pragma unroll
    for (int i=0;i<4;i++) { acc2[i][0]=0ull; acc2[i][1]=0ull; }
#pragma unroll 8
    for (int n = 0; n < 64; n++) {
        u64 a2[4], b2[2];
#pragma unroll
        for (int i=0;i<4;i++) DUP2(a2[i], sC[(ty*4+i)*65 + n]);
        PK2(b2[0], sB[(tx*4+0)*65 + n], sB[(tx*4+1)*65 + n]);
        PK2(b2[1], sB[(tx*4+2)*65 + n], sB[(tx*4+3)*65 + n]);
#pragma unroll
        for (int i=0;i<4;i++) {
            F2ACC(acc2[i][0], a2[i], b2[0]);
            F2ACC(acc2[i][1], a2[i], b2[1]);
        }
    }
#pragma unroll
    for (int i=0;i<4;i++) {
        int t = ty*4 + i;
        float pv[4];
        UPK2(pv[0], pv[1], acc2[i][0]);
        UPK2(pv[2], pv[3], acc2[i][1]);
#pragma unroll
        for (int j=0;j<4;j++) {
            int s = tx*4 + j;
            sP[t*65 + s] = (s <= t) ? pv[j] * __expf(sla[t] - sla[s]) * sdt[s] : 0.f;
        }
    }
    __syncthreads();

#pragma unroll
    for (int i=0;i<4;i++) { acc2[i][0]=0ull; acc2[i][1]=0ull; }
#pragma unroll 8
    for (int s = 0; s < 64; s++) {
        u64 a2[4], b2[2];
#pragma unroll
        for (int i=0;i<4;i++) DUP2(a2[i], sP[(ty*4+i)*65 + s]);
        PK2(b2[0], sX[s*65 + tx*4+0], sX[s*65 + tx*4+1]);
        PK2(b2[1], sX[s*65 + tx*4+2], sX[s*65 + tx*4+3]);
#pragma unroll
        for (int i=0;i<4;i++) {
            F2ACC(acc2[i][0], a2[i], b2[0]);
            F2ACC(acc2[i][1], a2[i], b2[1]);
        }
    }
#pragma unroll
    for (int i=0;i<4;i++) {
        int t = ty*4 + i;
        float4 y;
        UPK2(y.x, y.y, acc2[i][0]);
        UPK2(y.z, y.w, acc2[i][1]);
        *(float4*)(g_yc + (r0 + t)*DIN_ + h*64 + tx*4) = y;
    }
    __syncthreads();

#pragma unroll
    for (int i = 0; i < 4; i++) {
        int row = i * 16 + ty;
        float wv = sw[row];
#pragma unroll
        for (int j = 0; j < 4; j++)
            sP[row*65 + tx*4 + j] = wv * sX[row*65 + tx*4 + j];
    }
    __syncthreads();

#pragma unroll
    for (int i=0;i<4;i++) { acc2[i][0]=0ull; acc2[i][1]=0ull; }
#pragma unroll 8
    for (int s = 0; s < 64; s++) {
        u64 a2[4], b2[2];
#pragma unroll
        for (int i=0;i<4;i++) DUP2(a2[i], sB[s*65 + ty*4 + i]);
        PK2(b2[0], sP[s*65 + tx*4+0], sP[s*65 + tx*4+1]);
        PK2(b2[1], sP[s*65 + tx*4+2], sP[s*65 + tx*4+3]);
#pragma unroll
        for (int i=0;i<4;i++) {
            F2ACC(acc2[i][0], a2[i], b2[0]);
            F2ACC(acc2[i][1], a2[i], b2[1]);
        }
    }
    size_t so = ((size_t)bh * NCH + c) * (NN*PP);
#pragma unroll
    for (int i=0;i<4;i++) {
        int n = ty*4 + i;
        float4 v;
        UPK2(v.x, v.y, acc2[i][0]);
        UPK2(v.z, v.w, acc2[i][1]);
        *(float4*)(g_S + so + n*64 + tx*4) = v;
    }
    if (tid < 64) g_la[((size_t)bh*NCH + c)*CT + tid] = sla[tid];
    if (tid == 0) g_pa[bh*NCH + c] = __expf(sla[63]);
}

// ---------------- SSD phase B ------------------------------------------------
__global__ __launch_bounds__(256) void ssdB()
{
    int bh = blockIdx.x, tid = threadIdx.x;
    float h[16];
#pragma unroll
    for (int i=0;i<16;i++) h[i]=0.f;
    size_t base = (size_t)bh * NCH * (NN*PP);
    for (int c = 0; c < NCH; c++) {
        float pa = g_pa[bh*NCH + c];
        size_t cb = base + (size_t)c * (NN*PP);
#pragma unroll
        for (int i=0;i<16;i++) {
            size_t idx = cb + i*256 + tid;
            g_hin[idx] = h[i];
            h[i] = h[i]*pa + g_S[idx];
        }
    }
}

// ---------------- SSD phase C ------------------------------------------------
__global__ __launch_bounds__(256,2) void ssdC(const float* __restrict__ Ds)
{
    __shared__ float sCl[64*65];
    __shared__ float sH [64*65];
    __shared__ float sla2[64];
    const int c = blockIdx.x, h = blockIdx.y, b = blockIdx.z;
    const int tid = threadIdx.x;
    const int tx = tid & 15, ty = tid >> 4;
    const size_t r0 = (size_t)b * LL + c * CT;
    const int bh = b * HH + h;

    if (tid < 64) sla2[tid] = g_la[((size_t)bh*NCH + c)*CT + tid];
    __syncthreads();
#pragma unroll
    for (int i = 0; i < 4; i++) {
        int row = i * 16 + ty;
        float4 cv = *(const float4*)(g_dbc + (r0 + row)*XPROJ + 72 + tx*4);
        float e = __expf(sla2[row]);
        float4 hv = *(const float4*)(g_hin + ((size_t)bh*NCH + c)*(NN*PP) + row*64 + tx*4);
        sCl[row*65 + tx*4+0] = cv.x*e; sCl[row*65 + tx*4+1] = cv.y*e;
        sCl[row*65 + tx*4+2] = cv.z*e; sCl[row*65 + tx*4+3] = cv.w*e;
        sH [row*65 + tx*4+0] = hv.x;   sH [row*65 + tx*4+1] = hv.y;
        sH [row*65 + tx*4+2] = hv.z;   sH [row*65 + tx*4+3] = hv.w;
    }
    __syncthreads();

    u64 acc2[4][2];
#pragma unroll
    for (int i=0;i<4;i++) { acc2[i][0]=0ull; acc2[i][1]=0ull; }
#pragma unroll 8
    for (int n = 0; n < 64; n++) {
        u64 a2[4], b2[2];
#pragma unroll
        for (int i=0;i<4;i++) DUP2(a2[i], sCl[(ty*4+i)*65 + n]);
        PK2(b2[0], sH[n*65 + tx*4+0], sH[n*65 + tx*4+1]);
        PK2(b2[1], sH[n*65 + tx*4+2], sH[n*65 + tx*4+3]);
#pragma unroll
        for (int i=0;i<4;i++) {
            F2ACC(acc2[i][0], a2[i], b2[0]);
            F2ACC(acc2[i][1], a2[i], b2[1]);
        }
    }
    float dsh = Ds[h];
#pragma unroll
    for (int i=0;i<4;i++) {
        int t = ty*4 + i;
        float* yp = g_yc + (r0 + t)*DIN_ + h*64 + tx*4;
        float4 y1 = *(float4*)yp;
        size_t uoff = (r0 + t)*DIN_ + h*64 + tx*4;
        float4 xv = ld4hl(g_uh + uoff, g_ul + uoff);
        float a0,a1,a2v,a3;
        UPK2(a0, a1, acc2[i][0]);
        UPK2(a2v, a3, acc2[i][1]);
        y1.x += a0 + dsh*xv.x;
        y1.y += a1 + dsh*xv.y;
        y1.z += a2v + dsh*xv.z;
        y1.w += a3 + dsh*xv.w;
        *(float4*)yp = y1;
    }
}

// ---------------- launch ----------------------------------------------------
extern "C" void kernel_launch(void* const* d_in, const int* in_sizes, int n_in,
                              void* d_out, int out_size)
{
    const float* src     = (const float*)d_in[0];
    const float* ln_w    = (const float*)d_in[1];
    const float* ln_b    = (const float*)d_in[2];
    const float* W_in    = (const float*)d_in[3];
    const float* conv_w  = (const float*)d_in[4];
    const float* conv_b  = (const float*)d_in[5];
    const float* W_xproj = (const float*)d_in[6];
    const float* dt_bias = (const float*)d_in[7];
    const float* A_log   = (const float*)d_in[8];
    const float* Ds      = (const float*)d_in[9];
    const float* oln_w   = (const float*)d_in[10];
    const float* oln_b   = (const float*)d_in[11];
    const float* W_out   = (const float*)d_in[12];
    float* out = (float*)d_out;

    __nv_bfloat16 *p_xh,*p_xl,*p_uh,*p_ul,*p_yh,*p_yl;
    __nv_bfloat16 *p_w1h,*p_w1l,*p_w2h,*p_w2l,*p_w3h,*p_w3l;
    float *p_ur,*p_dbc,*p_yc;
    cudaGetSymbolAddress((void**)&p_xh, g_xh);   cudaGetSymbolAddress((void**)&p_xl, g_xl);
    cudaGetSymbolAddress((void**)&p_uh, g_uh);   cudaGetSymbolAddress((void**)&p_ul, g_ul);
    cudaGetSymbolAddress((void**)&p_yh, g_yh);   cudaGetSymbolAddress((void**)&p_yl, g_yl);
    cudaGetSymbolAddress((void**)&p_w1h, g_w1h); cudaGetSymbolAddress((void**)&p_w1l, g_w1l);
    cudaGetSymbolAddress((void**)&p_w2h, g_w2h); cudaGetSymbolAddress((void**)&p_w2l, g_w2l);
    cudaGetSymbolAddress((void**)&p_w3h, g_w3h); cudaGetSymbolAddress((void**)&p_w3l, g_w3l);
    cudaGetSymbolAddress((void**)&p_ur, g_ur);
    cudaGetSymbolAddress((void**)&p_dbc, g_dbc);
    cudaGetSymbolAddress((void**)&p_yc, g_yc);

    const int ASMEM = 67328;
    cudaFuncSetAttribute(ssdA, cudaFuncAttributeMaxDynamicSharedMemorySize, ASMEM);
    cudaFuncSetAttribute(hgemm, cudaFuncAttributeMaxDynamicSharedMemorySize, HSMEM);

    wprep<<<(DD*DIN_ + 255)/256, 256>>>(W_in,    p_w1h, p_w1l, DD,   DIN_);
    wprep<<<(DIN_*XPROJ + 255)/256, 256>>>(W_xproj, p_w2h, p_w2l, DIN_, XPROJ);
    wprep<<<(DIN_*DD + 255)/256, 256>>>(W_out,   p_w3h, p_w3l, DIN_, DD);

    // 1) LN1 -> bf16 hi/lo
    ln_bf<DD><<<ROWS, 256>>>(src, ln_w, ln_b, p_xh, p_xl);
    // 2) ur = x @ W_in  (N=512 -> 8 n-tiles)
    hgemm<<<dim3(ROWS/128, 8), 256, HSMEM>>>(p_xh, p_xl, p_w1h, p_w1l, p_ur, nullptr,
                                             ROWS, DIN_, DD);
    // 3) u = gelu(conv3(ur)+b) -> bf16 hi/lo
    convgelu_k<<<(ROWS*DIN_/4 + 255)/256, 256>>>(conv_w, conv_b);
    // 4) dbc = u @ W_xproj: main 128 cols (2 n-tiles) + skinny last 8
    hgemm<<<dim3(ROWS/128, 2), 256, HSMEM>>>(p_uh, p_ul, p_w2h, p_w2l, p_dbc, nullptr,
                                             ROWS, XPROJ, DIN_);
    skinny8<<<ROWS/8, 256>>>(W_xproj);
    // 5) chunked scan
    ssdA<<<dim3(NCH, HH, BB), 256, ASMEM>>>(dt_bias, A_log);
    ssdB<<<BB*HH, 256>>>();
    ssdC<<<dim3(NCH, HH, BB), 256>>>(Ds);
    // 6) oln -> bf16 hi/lo
    ln_bf<DIN_><<<ROWS, 256>>>(p_yc, oln_w, oln_b, p_yh, p_yl);
    // 7) out = src + yln @ W_out (N=256 -> 4 n-tiles)
    hgemm<<<dim3(ROWS/128, 4), 256, HSMEM>>>(p_yh, p_yl, p_w3h, p_w3l, out, src,
                                             ROWS, DD, DIN_);
}

// round 14
// speedup vs baseline: 1.2209x; 1.1978x over previous
#include <cuda_runtime.h>
#include <cuda_bf16.h>
#include <math.h>
#include <stdint.h>

#define BB   8
#define LL   2048
#define DD   256
#define DIN_ 512
#define NN   64
#define PP   64
#define HH   8
#define ROWS (BB*LL)          // 16384
#define XPROJ (HH + 2*NN)     // 136
#define NCH  32
#define CT   64

typedef unsigned long long u64;

// ---------------- scratch (device globals) ---------------------------------
__device__ __nv_bfloat16 g_xh[ROWS*DD],   g_xl[ROWS*DD];
__device__ float         g_ur [ROWS*DIN_];
__device__ __nv_bfloat16 g_uh[ROWS*DIN_], g_ul[ROWS*DIN_];
__device__ float         g_dbc[ROWS*XPROJ];
__device__ float         g_yc [ROWS*DIN_];
__device__ __nv_bfloat16 g_yh[ROWS*DIN_], g_yl[ROWS*DIN_];
__device__ float         g_S  [BB*HH*NCH*NN*PP];
__device__ float         g_hin[BB*HH*NCH*NN*PP];
__device__ float         g_la [BB*HH*NCH*CT];
__device__ float         g_pa [BB*HH*NCH];
__device__ __nv_bfloat16 g_w1h[DIN_*DD],    g_w1l[DIN_*DD];
__device__ __nv_bfloat16 g_w2h[XPROJ*DIN_], g_w2l[XPROJ*DIN_];
__device__ __nv_bfloat16 g_w3h[DD*DIN_],    g_w3l[DD*DIN_];

// ---------------- helpers ---------------------------------------------------
__device__ __forceinline__ uint32_t smem_u32(const void* p){
    uint32_t a;
    asm("{ .reg .u64 t; cvta.to.shared.u64 t, %1; cvt.u32.u64 %0, t; }" : "=r"(a) : "l"(p));
    return a;
}
__device__ __forceinline__ void cp16(uint32_t dst, const void* src, int sz){
    asm volatile("cp.async.ca.shared.global [%0], [%1], 16, %2;"
                 :: "r"(dst), "l"(src), "r"(sz) : "memory");
}
#define CP_COMMIT() asm volatile("cp.async.commit_group;" ::: "memory")
#define CP_WAIT1()  asm volatile("cp.async.wait_group 1;" ::: "memory")
#define CP_WAIT0()  asm volatile("cp.async.wait_group 0;" ::: "memory")

#define LDSM4(r, a) asm volatile( \
    "ldmatrix.sync.aligned.m8n8.x4.shared.b16 {%0,%1,%2,%3}, [%4];" \
    : "=r"((r)[0]),"=r"((r)[1]),"=r"((r)[2]),"=r"((r)[3]) : "r"(a))

__device__ __forceinline__ void mma_bf16(float* d, const uint32_t* a, const uint32_t* b){
    asm volatile("mma.sync.aligned.m16n8k16.row.col.f32.bf16.bf16.f32 "
        "{%0,%1,%2,%3}, {%4,%5,%6,%7}, {%8,%9}, {%0,%1,%2,%3};"
        : "+f"(d[0]), "+f"(d[1]), "+f"(d[2]), "+f"(d[3])
        : "r"(a[0]), "r"(a[1]), "r"(a[2]), "r"(a[3]), "r"(b[0]), "r"(b[1]));
}

// packed f32x2
#define PK2(d, lo, hi) asm("mov.b64 %0, {%1,%2};" : "=l"(d) : "r"(__float_as_uint(lo)), "r"(__float_as_uint(hi)))
#define DUP2(d, x)     asm("mov.b64 %0, {%1,%1};" : "=l"(d) : "r"(__float_as_uint(x)))
#define UPK2(lo, hi, v) do { uint32_t _a,_b; asm("mov.b64 {%0,%1}, %2;" : "=r"(_a), "=r"(_b) : "l"(v)); lo=__uint_as_float(_a); hi=__uint_as_float(_b); } while(0)
#define F2ACC(d, a, b) asm("fma.rn.f32x2 %0, %1, %2, %0;" : "+l"(d) : "l"(a), "l"(b))

__device__ __forceinline__ float4 ld4hl(const __nv_bfloat16* hp, const __nv_bfloat16* lp){
    uint2 vh = *(const uint2*)hp;
    uint2 vl = *(const uint2*)lp;
    __nv_bfloat162 h0 = *(__nv_bfloat162*)&vh.x, h1 = *(__nv_bfloat162*)&vh.y;
    __nv_bfloat162 l0 = *(__nv_bfloat162*)&vl.x, l1 = *(__nv_bfloat162*)&vl.y;
    float4 r;
    r.x = __bfloat162float(h0.x) + __bfloat162float(l0.x);
    r.y = __bfloat162float(h0.y) + __bfloat162float(l0.y);
    r.z = __bfloat162float(h1.x) + __bfloat162float(l1.x);
    r.w = __bfloat162float(h1.y) + __bfloat162float(l1.y);
    return r;
}

// ---------------- weight prep ------------------------------------------------
__global__ __launch_bounds__(256) void wprep(const float* __restrict__ W,
        __nv_bfloat16* __restrict__ oh, __nv_bfloat16* __restrict__ ol, int K, int N)
{
    int idx = blockIdx.x * 256 + threadIdx.x;
    if (idx >= K * N) return;
    int n = idx / K, k = idx - n * K;
    float v = W[(size_t)k * N + n];
    __nv_bfloat16 hh = __float2bfloat16(v);
    oh[idx] = hh;
    ol[idx] = __float2bfloat16(v - __bfloat162float(hh));
}

// ---------------- LayerNorm -> bf16 hi/lo (warp per row, vectorized) --------
template<int W>
__global__ __launch_bounds__(256) void ln_bf(const float* __restrict__ x,
        const float* __restrict__ w, const float* __restrict__ b,
        __nv_bfloat16* __restrict__ yh, __nv_bfloat16* __restrict__ yl)
{
    constexpr int E4 = W / 128;             // float4s per lane (2 or 4)
    const int lane = threadIdx.x & 31;
    const int row  = blockIdx.x * 8 + (threadIdx.x >> 5);
    const float4* xr = (const float4*)(x + (size_t)row * W);
    float4 v[E4];
    float s = 0.f, q = 0.f;
#pragma unroll
    for (int i = 0; i < E4; i++) {
        v[i] = xr[lane + 32*i];
        s += v[i].x + v[i].y + v[i].z + v[i].w;
        q += v[i].x*v[i].x + v[i].y*v[i].y + v[i].z*v[i].z + v[i].w*v[i].w;
    }
#pragma unroll
    for (int o = 16; o; o >>= 1) {
        s += __shfl_xor_sync(0xffffffffu, s, o);
        q += __shfl_xor_sync(0xffffffffu, q, o);
    }
    float mean = s / (float)W;
    float rstd = rsqrtf(q / (float)W - mean*mean + 1e-5f);
    const float4* w4 = (const float4*)w;
    const float4* b4 = (const float4*)b;
#pragma unroll
    for (int i = 0; i < E4; i++) {
        int c4 = lane + 32*i;
        float4 wv = w4[c4], bv = b4[c4];
        float o0 = (v[i].x - mean)*rstd*wv.x + bv.x;
        float o1 = (v[i].y - mean)*rstd*wv.y + bv.y;
        float o2 = (v[i].z - mean)*rstd*wv.z + bv.z;
        float o3 = (v[i].w - mean)*rstd*wv.w + bv.w;
        __nv_bfloat16 hh[4], ll[4];
        hh[0] = __float2bfloat16(o0); ll[0] = __float2bfloat16(o0 - __bfloat162float(hh[0]));
        hh[1] = __float2bfloat16(o1); ll[1] = __float2bfloat16(o1 - __bfloat162float(hh[1]));
        hh[2] = __float2bfloat16(o2); ll[2] = __float2bfloat16(o2 - __bfloat162float(hh[2]));
        hh[3] = __float2bfloat16(o3); ll[3] = __float2bfloat16(o3 - __bfloat162float(hh[3]));
        *(uint2*)(yh + (size_t)row*W + c4*4) = *(uint2*)hh;
        *(uint2*)(yl + (size_t)row*W + c4*4) = *(uint2*)ll;
    }
}

// ---------------- HMMA bf16-split GEMM, BM128 x BN64, 2 CTAs/SM -------------
#define HA_OFF  0
#define HAL_OFF 10240
#define HBH_OFF 20480
#define HBL_OFF 25600
#define HSTG    30720
#define HSMEM   61440
__global__ __launch_bounds__(256,2) void hgemm(
    const __nv_bfloat16* __restrict__ Ah, const __nv_bfloat16* __restrict__ Al,
    const __nv_bfloat16* __restrict__ Bh, const __nv_bfloat16* __restrict__ Bl,
    float* __restrict__ C, const float* __restrict__ addend,
    int M, int N, int K)
{
    extern __shared__ char hsm[];
    const uint32_t sb = smem_u32(hsm);
    const int tid = threadIdx.x, wid = tid >> 5, lane = tid & 31;
    const int m0 = blockIdx.x * 128, n0 = blockIdx.y * 64;
    const int wm = (wid >> 1) * 32, wn = (wid & 1) * 32;
    const int NC = K >> 5;

    float acc[2][4][4];
#pragma unroll
    for (int i = 0; i < 2; i++)
#pragma unroll
        for (int j = 0; j < 4; j++)
#pragma unroll
            for (int q = 0; q < 4; q++) acc[i][j][q] = 0.f;

    auto issue = [&](int c){
        int s = c & 1;
        int k0 = c << 5;
        uint32_t stg = sb + s * HSTG;
#pragma unroll
        for (int i = 0; i < 6; i++) {
            int idx = tid + i * 256;
            if (idx < 1024) {
                int mat = idx >> 9, w = idx & 511, row = w >> 2, cc = w & 3;
                uint32_t dst = stg + (mat ? HAL_OFF : HA_OFF) + row*80 + cc*16;
                const __nv_bfloat16* Ap = mat ? Al : Ah;
                cp16(dst, Ap + (size_t)(m0 + row) * K + k0 + cc*8, 16);
            } else {
                int j = idx - 1024;
                int mat = j >> 8, w = j & 255, row = w >> 2, cc = w & 3;
                uint32_t dst = stg + (mat ? HBL_OFF : HBH_OFF) + row*80 + cc*16;
                int n = n0 + row;
                int ok = (n < N);
                const __nv_bfloat16* Bp = mat ? Bl : Bh;
                cp16(dst, Bp + (size_t)(ok ? n : 0) * K + k0 + cc*8, ok ? 16 : 0);
            }
        }
    };

    const int rA  = wm + (lane & 15);
    const int kAo = (lane >> 4) * 16;
    const int rB  = wn + (lane & 7) + ((lane >> 4) & 1) * 8;
    const int kBo = ((lane >> 3) & 1) * 16;

    issue(0); CP_COMMIT();

    for (int c = 0; c < NC; c++) {
        int s = c & 1;
        if (c + 1 < NC) { issue(c + 1); CP_COMMIT(); CP_WAIT1(); }
        else            { CP_WAIT0(); }
        __syncthreads();
        uint32_t st = sb + s * HSTG;
#pragma unroll
        for (int ks = 0; ks < 2; ks++) {
            int ksb = ks * 32;
            uint32_t ah[2][4], al[2][4];
            uint32_t aAdr = st + HA_OFF + rA*80 + ksb + kAo;
            LDSM4(ah[0], aAdr);
            LDSM4(ah[1], aAdr + 16*80);
            LDSM4(al[0], aAdr + (HAL_OFF - HA_OFF));
            LDSM4(al[1], aAdr + (HAL_OFF - HA_OFF) + 16*80);
            uint32_t bh[4][2], bl[4][2];
            {
                uint32_t r4[4];
                uint32_t bAdr = st + HBH_OFF + rB*80 + ksb + kBo;
                LDSM4(r4, bAdr);
                bh[0][0]=r4[0]; bh[0][1]=r4[1]; bh[1][0]=r4[2]; bh[1][1]=r4[3];
                LDSM4(r4, bAdr + 16*80);
                bh[2][0]=r4[0]; bh[2][1]=r4[1]; bh[3][0]=r4[2]; bh[3][1]=r4[3];
                LDSM4(r4, bAdr + (HBL_OFF - HBH_OFF));
                bl[0][0]=r4[0]; bl[0][1]=r4[1]; bl[1][0]=r4[2]; bl[1][1]=r4[3];
                LDSM4(r4, bAdr + (HBL_OFF - HBH_OFF) + 16*80);
                bl[2][0]=r4[0]; bl[2][1]=r4[1]; bl[3][0]=r4[2]; bl[3][1]=r4[3];
            }
#pragma unroll
            for (int i = 0; i < 2; i++)
#pragma unroll
                for (int j = 0; j < 4; j++) {
                    mma_bf16(acc[i][j], ah[i], bh[j]);
                    mma_bf16(acc[i][j], ah[i], bl[j]);
                    mma_bf16(acc[i][j], al[i], bh[j]);
                }
        }
        __syncthreads();
    }

    const int g = lane >> 2, tg = lane & 3;
#pragma unroll
    for (int i = 0; i < 2; i++) {
#pragma unroll
        for (int j = 0; j < 4; j++) {
            int col = n0 + wn + j*8 + tg*2;
            if (col >= N) continue;
            int mA = m0 + wm + i*16 + g;
            int mB = mA + 8;
            float2 v0 = make_float2(acc[i][j][0], acc[i][j][1]);
            float2 v1 = make_float2(acc[i][j][2], acc[i][j][3]);
            if (addend) {
                float2 a0 = *(const float2*)(addend + (size_t)mA * N + col);
                float2 a1 = *(const float2*)(addend + (size_t)mB * N + col);
                v0.x += a0.x; v0.y += a0.y; v1.x += a1.x; v1.y += a1.y;
            }
            *(float2*)(C + (size_t)mA * N + col) = v0;
            *(float2*)(C + (size_t)mB * N + col) = v1;
        }
    }
}

// ---------------- skinny GEMM: dbc cols 128..135 ----------------------------
__global__ __launch_bounds__(256) void skinny8(const float* __restrict__ Wx)
{
    __shared__ float sW[512*9];
    const int tid = threadIdx.x;
#pragma unroll
    for (int t = 0; t < 16; t++) {
        int idx = tid + t * 256;
        int k = idx >> 3, c = idx & 7;
        sW[k*9 + c] = Wx[(size_t)k * XPROJ + 128 + c];
    }
    __syncthreads();
    int row = blockIdx.x * 8 + (tid >> 5);
    int lane = tid & 31;
    float acc[8];
#pragma unroll
    for (int c = 0; c < 8; c++) acc[c] = 0.f;
    const __nv_bfloat16* uh = g_uh + (size_t)row * DIN_;
    const __nv_bfloat16* ul = g_ul + (size_t)row * DIN_;
#pragma unroll
    for (int i = 0; i < 4; i++) {
        int k = (lane + i * 32) * 4;
        float4 uv = ld4hl(uh + k, ul + k);
        float u4[4] = {uv.x, uv.y, uv.z, uv.w};
#pragma unroll
        for (int q = 0; q < 4; q++)
#pragma unroll
            for (int c = 0; c < 8; c++)
                acc[c] = fmaf(u4[q], sW[(k+q)*9 + c], acc[c]);
    }
#pragma unroll
    for (int o = 16; o; o >>= 1)
#pragma unroll
        for (int c = 0; c < 8; c++)
            acc[c] += __shfl_xor_sync(0xffffffffu, acc[c], o);
    if (lane == 0) {
#pragma unroll
        for (int c = 0; c < 8; c++)
            g_dbc[(size_t)row * XPROJ + 128 + c] = acc[c];
    }
}

// ---------------- depthwise conv3 + GELU -> bf16 hi/lo ----------------------
__global__ __launch_bounds__(256) void convgelu_k(const float* __restrict__ cw,
                                                  const float* __restrict__ cb)
{
    int idx = blockIdx.x * 256 + threadIdx.x;       // over ROWS*DIN_/4
    if (idx >= ROWS * DIN_ / 4) return;
    int cg = idx & 127;
    int l  = (idx >> 7) & (LL - 1);
    float4 mid = *(const float4*)(g_ur + (size_t)idx*4);
    float4 lft = make_float4(0,0,0,0), rgt = make_float4(0,0,0,0);
    if (l > 0)      lft = *(const float4*)(g_ur + (size_t)(idx - 128)*4);
    if (l < LL - 1) rgt = *(const float4*)(g_ur + (size_t)(idx + 128)*4);
    float m[4] = {mid.x, mid.y, mid.z, mid.w};
    float a[4] = {lft.x, lft.y, lft.z, lft.w};
    float r[4] = {rgt.x, rgt.y, rgt.z, rgt.w};
    __nv_bfloat16 oh[4], ol[4];
#pragma unroll
    for (int q = 0; q < 4; q++) {
        int c = cg * 4 + q;
        float x = a[q]*cw[c*3] + m[q]*cw[c*3+1] + r[q]*cw[c*3+2] + cb[c];
        float g = 0.5f * x * (1.f + erff(x * 0.7071067811865476f));
        oh[q] = __float2bfloat16(g);
        ol[q] = __float2bfloat16(g - __bfloat162float(oh[q]));
    }
    *(uint2*)(g_uh + (size_t)idx*4) = *(uint2*)oh;
    *(uint2*)(g_ul + (size_t)idx*4) = *(uint2*)ol;
}

// ---------------- SSD phase A ------------------------------------------------
__global__ __launch_bounds__(256,2) void ssdA(const float* __restrict__ dt_bias,
                                              const float* __restrict__ A_log)
{
    extern __shared__ float sm[];
    float* sB  = sm;            // 64 x 65
    float* sC  = sm + 4160;
    float* sX  = sm + 8320;
    float* sP  = sm + 12480;
    float* sdt = sm + 16640;
    float* sla = sdt + 64;
    float* sw  = sla + 64;
    const int c = blockIdx.x, h = blockIdx.y, b = blockIdx.z;
    const int tid = threadIdx.x;
    const int tx = tid & 15, ty = tid >> 4;
    const size_t r0 = (size_t)b * LL + c * CT;
    const int bh = b * HH + h;

#pragma unroll
    for (int i = 0; i < 4; i++) {
        int row = i * 16 + ty;
        const float* dr = g_dbc + (r0 + row) * XPROJ;
        float4 bv = *(const float4*)(dr + 8  + tx*4);
        float4 cv = *(const float4*)(dr + 72 + tx*4);
        size_t uoff = (r0 + row)*DIN_ + h*64 + tx*4;
        float4 xv = ld4hl(g_uh + uoff, g_ul + uoff);
        sB[row*65 + tx*4+0]=bv.x; sB[row*65 + tx*4+1]=bv.y;
        sB[row*65 + tx*4+2]=bv.z; sB[row*65 + tx*4+3]=bv.w;
        sC[row*65 + tx*4+0]=cv.x; sC[row*65 + tx*4+1]=cv.y;
        sC[row*65 + tx*4+2]=cv.z; sC[row*65 + tx*4+3]=cv.w;
        sX[row*65 + tx*4+0]=xv.x; sX[row*65 + tx*4+1]=xv.y;
        sX[row*65 + tx*4+2]=xv.z; sX[row*65 + tx*4+3]=xv.w;
    }
    if (tid < 64) {
        float xx = g_dbc[(r0 + tid)*XPROJ + h] + dt_bias[h];
        float dt = (xx > 20.f) ? xx : log1pf(expf(xx));
        float la = -dt * expf(A_log[h]);
        int lane = tid & 31;
        float v = la;
#pragma unroll
        for (int o = 1; o < 32; o <<= 1) {
            float pv = __shfl_up_sync(0xffffffffu, v, o);
            if (lane >= o) v += pv;
        }
        sdt[tid] = dt;
        sla[tid] = v;
    }
    __syncthreads();
    if (tid >= 32 && tid < 64) sla[tid] += sla[31];
    __syncthreads();
    if (tid < 64) sw[tid] = sdt[tid] * __expf(sla[63] - sla[tid]);
    __syncthreads();

    u64 acc2[4][2];
#pragma unroll
    for (int i=0;i<4;i++) { acc2[i][0]=0ull; acc2[i][1]=0ull; }
#pragma unroll 8
    for (int n = 0; n < 64; n++) {
        u64 a2[4], b2[2];
#pragma unroll
        for (int i=0;i<4;i++) DUP2(a2[i], sC[(ty*4+i)*65 + n]);
        PK2(b2[0], sB[(tx*4+0)*65 + n], sB[(tx*4+1)*65 + n]);
        PK2(b2[1], sB[(tx*4+2)*65 + n], sB[(tx*4+3)*65 + n]);
#pragma unroll
        for (int i=0;i<4;i++) {
            F2ACC(acc2[i][0], a2[i], b2[0]);
            F2ACC(acc2[i][1], a2[i], b2[1]);
        }
    }
#pragma unroll
    for (int i=0;i<4;i++) {
        int t = ty*4 + i;
        float pv[4];
        UPK2(pv[0], pv[1], acc2[i][0]);
        UPK2(pv[2], pv[3], acc2[i][1]);
#pragma unroll
        for (int j=0;j<4;j++) {
            int s = tx*4 + j;
            sP[t*65 + s] = (s <= t) ? pv[j] * __expf(sla[t] - sla[s]) * sdt[s] : 0.f;
        }
    }
    __syncthreads();

#pragma unroll
    for (int i=0;i<4;i++) { acc2[i][0]=0ull; acc2[i][1]=0ull; }
#pragma unroll 8
    for (int s = 0; s < 64; s++) {
        u64 a2[4], b2[2];
#pragma unroll
        for (int i=0;i<4;i++) DUP2(a2[i], sP[(ty*4+i)*65 + s]);
        PK2(b2[0], sX[s*65 + tx*4+0], sX[s*65 + tx*4+1]);
        PK2(b2[1], sX[s*65 + tx*4+2], sX[s*65 + tx*4+3]);
#pragma unroll
        for (int i=0;i<4;i++) {
            F2ACC(acc2[i][0], a2[i], b2[0]);
            F2ACC(acc2[i][1], a2[i], b2[1]);
        }
    }
#pragma unroll
    for (int i=0;i<4;i++) {
        int t = ty*4 + i;
        float4 y;
        UPK2(y.x, y.y, acc2[i][0]);
        UPK2(y.z, y.w, acc2[i][1]);
        *(float4*)(g_yc + (r0 + t)*DIN_ + h*64 + tx*4) = y;
    }
    __syncthreads();

#pragma unroll
    for (int i = 0; i < 4; i++) {
        int row = i * 16 + ty;
        float wv = sw[row];
#pragma unroll
        for (int j = 0; j < 4; j++)
            sP[row*65 + tx*4 + j] = wv * sX[row*65 + tx*4 + j];
    }
    __syncthreads();

#pragma unroll
    for (int i=0;i<4;i++) { acc2[i][0]=0ull; acc2[i][1]=0ull; }
#pragma unroll 8
    for (int s = 0; s < 64; s++) {
        u64 a2[4], b2[2];
#pragma unroll
        for (int i=0;i<4;i++) DUP2(a2[i], sB[s*65 + ty*4 + i]);
        PK2(b2[0], sP[s*65 + tx*4+0], sP[s*65 + tx*4+1]);
        PK2(b2[1], sP[s*65 + tx*4+2], sP[s*65 + tx*4+3]);
#pragma unroll
        for (int i=0;i<4;i++) {
            F2ACC(acc2[i][0], a2[i], b2[0]);
            F2ACC(acc2[i][1], a2[i], b2[1]);
        }
    }
    size_t so = ((size_t)bh * NCH + c) * (NN*PP);
#pragma unroll
    for (int i=0;i<4;i++) {
        int n = ty*4 + i;
        float4 v;
        UPK2(v.x, v.y, acc2[i][0]);
        UPK2(v.z, v.w, acc2[i][1]);
        *(float4*)(g_S + so + n*64 + tx*4) = v;
    }
    if (tid < 64) g_la[((size_t)bh*NCH + c)*CT + tid] = sla[tid];
    if (tid == 0) g_pa[bh*NCH + c] = __expf(sla[63]);
}

// ---------------- SSD phase B (float4) ---------------------------------------
__global__ __launch_bounds__(256) void ssdB()
{
    int bh = blockIdx.x, tid = threadIdx.x;
    float4 h[4];
#pragma unroll
    for (int i=0;i<4;i++) h[i] = make_float4(0,0,0,0);
    const float4* S4 = (const float4*)g_S;
    float4* H4 = (float4*)g_hin;
    size_t base = (size_t)bh * NCH * (NN*PP/4);
    for (int c = 0; c < NCH; c++) {
        float pa = g_pa[bh*NCH + c];
        size_t cb = base + (size_t)c * (NN*PP/4);
#pragma unroll
        for (int i=0;i<4;i++) {
            size_t idx = cb + i*256 + tid;
            H4[idx] = h[i];
            float4 sv = S4[idx];
            h[i].x = h[i].x*pa + sv.x;
            h[i].y = h[i].y*pa + sv.y;
            h[i].z = h[i].z*pa + sv.z;
            h[i].w = h[i].w*pa + sv.w;
        }
    }
}

// ---------------- SSD phase C ------------------------------------------------
__global__ __launch_bounds__(256,2) void ssdC(const float* __restrict__ Ds)
{
    __shared__ float sCl[64*65];
    __shared__ float sH [64*65];
    __shared__ float sla2[64];
    const int c = blockIdx.x, h = blockIdx.y, b = blockIdx.z;
    const int tid = threadIdx.x;
    const int tx = tid & 15, ty = tid >> 4;
    const size_t r0 = (size_t)b * LL + c * CT;
    const int bh = b * HH + h;

    if (tid < 64) sla2[tid] = g_la[((size_t)bh*NCH + c)*CT + tid];
    __syncthreads();
#pragma unroll
    for (int i = 0; i < 4; i++) {
        int row = i * 16 + ty;
        float4 cv = *(const float4*)(g_dbc + (r0 + row)*XPROJ + 72 + tx*4);
        float e = __expf(sla2[row]);
        float4 hv = *(const float4*)(g_hin + ((size_t)bh*NCH + c)*(NN*PP) + row*64 + tx*4);
        sCl[row*65 + tx*4+0] = cv.x*e; sCl[row*65 + tx*4+1] = cv.y*e;
        sCl[row*65 + tx*4+2] = cv.z*e; sCl[row*65 + tx*4+3] = cv.w*e;
        sH [row*65 + tx*4+0] = hv.x;   sH [row*65 + tx*4+1] = hv.y;
        sH [row*65 + tx*4+2] = hv.z;   sH [row*65 + tx*4+3] = hv.w;
    }
    __syncthreads();

    u64 acc2[4][2];
#pragma unroll
    for (int i=0;i<4;i++) { acc2[i][0]=0ull; acc2[i][1]=0ull; }
#pragma unroll 8
    for (int n = 0; n < 64; n++) {
        u64 a2[4], b2[2];
#pragma unroll
        for (int i=0;i<4;i++) DUP2(a2[i], sCl[(ty*4+i)*65 + n]);
        PK2(b2[0], sH[n*65 + tx*4+0], sH[n*65 + tx*4+1]);
        PK2(b2[1], sH[n*65 + tx*4+2], sH[n*65 + tx*4+3]);
#pragma unroll
        for (int i=0;i<4;i++) {
            F2ACC(acc2[i][0], a2[i], b2[0]);
            F2ACC(acc2[i][1], a2[i], b2[1]);
        }
    }
    float dsh = Ds[h];
#pragma unroll
    for (int i=0;i<4;i++) {
        int t = ty*4 + i;
        float* yp = g_yc + (r0 + t)*DIN_ + h*64 + tx*4;
        float4 y1 = *(float4*)yp;
        size_t uoff = (r0 + t)*DIN_ + h*64 + tx*4;
        float4 xv = ld4hl(g_uh + uoff, g_ul + uoff);
        float a0,a1,a2v,a3;
        UPK2(a0, a1, acc2[i][0]);
        UPK2(a2v, a3, acc2[i][1]);
        y1.x += a0 + dsh*xv.x;
        y1.y += a1 + dsh*xv.y;
        y1.z += a2v + dsh*xv.z;
        y1.w += a3 + dsh*xv.w;
        *(float4*)yp = y1;
    }
}

// ---------------- launch ----------------------------------------------------
extern "C" void kernel_launch(void* const* d_in, const int* in_sizes, int n_in,
                              void* d_out, int out_size)
{
    const float* src     = (const float*)d_in[0];
    const float* ln_w    = (const float*)d_in[1];
    const float* ln_b    = (const float*)d_in[2];
    const float* W_in    = (const float*)d_in[3];
    const float* conv_w  = (const float*)d_in[4];
    const float* conv_b  = (const float*)d_in[5];
    const float* W_xproj = (const float*)d_in[6];
    const float* dt_bias = (const float*)d_in[7];
    const float* A_log   = (const float*)d_in[8];
    const float* Ds      = (const float*)d_in[9];
    const float* oln_w   = (const float*)d_in[10];
    const float* oln_b   = (const float*)d_in[11];
    const float* W_out   = (const float*)d_in[12];
    float* out = (float*)d_out;

    __nv_bfloat16 *p_xh,*p_xl,*p_uh,*p_ul,*p_yh,*p_yl;
    __nv_bfloat16 *p_w1h,*p_w1l,*p_w2h,*p_w2l,*p_w3h,*p_w3l;
    float *p_ur,*p_dbc,*p_yc;
    cudaGetSymbolAddress((void**)&p_xh, g_xh);   cudaGetSymbolAddress((void**)&p_xl, g_xl);
    cudaGetSymbolAddress((void**)&p_uh, g_uh);   cudaGetSymbolAddress((void**)&p_ul, g_ul);
    cudaGetSymbolAddress((void**)&p_yh, g_yh);   cudaGetSymbolAddress((void**)&p_yl, g_yl);
    cudaGetSymbolAddress((void**)&p_w1h, g_w1h); cudaGetSymbolAddress((void**)&p_w1l, g_w1l);
    cudaGetSymbolAddress((void**)&p_w2h, g_w2h); cudaGetSymbolAddress((void**)&p_w2l, g_w2l);
    cudaGetSymbolAddress((void**)&p_w3h, g_w3h); cudaGetSymbolAddress((void**)&p_w3l, g_w3l);
    cudaGetSymbolAddress((void**)&p_ur, g_ur);
    cudaGetSymbolAddress((void**)&p_dbc, g_dbc);
    cudaGetSymbolAddress((void**)&p_yc, g_yc);

    const int ASMEM = 67328;
    cudaFuncSetAttribute(ssdA, cudaFuncAttributeMaxDynamicSharedMemorySize, ASMEM);
    cudaFuncSetAttribute(hgemm, cudaFuncAttributeMaxDynamicSharedMemorySize, HSMEM);

    wprep<<<(DD*DIN_ + 255)/256, 256>>>(W_in,    p_w1h, p_w1l, DD,   DIN_);
    wprep<<<(DIN_*XPROJ + 255)/256, 256>>>(W_xproj, p_w2h, p_w2l, DIN_, XPROJ);
    wprep<<<(DIN_*DD + 255)/256, 256>>>(W_out,   p_w3h, p_w3l, DIN_, DD);

    // 1) LN1 -> bf16 hi/lo (warp per row)
    ln_bf<DD><<<ROWS/8, 256>>>(src, ln_w, ln_b, p_xh, p_xl);
    // 2) ur = x @ W_in
    hgemm<<<dim3(ROWS/128, 8), 256, HSMEM>>>(p_xh, p_xl, p_w1h, p_w1l, p_ur, nullptr,
                                             ROWS, DIN_, DD);
    // 3) u = gelu(conv3(ur)+b) -> bf16 hi/lo
    convgelu_k<<<(ROWS*DIN_/4 + 255)/256, 256>>>(conv_w, conv_b);
    // 4) dbc = u @ W_xproj
    hgemm<<<dim3(ROWS/128, 2), 256, HSMEM>>>(p_uh, p_ul, p_w2h, p_w2l, p_dbc, nullptr,
                                             ROWS, XPROJ, DIN_);
    skinny8<<<ROWS/8, 256>>>(W_xproj);
    // 5) chunked scan
    ssdA<<<dim3(NCH, HH, BB), 256, ASMEM>>>(dt_bias, A_log);
    ssdB<<<BB*HH, 256>>>();
    ssdC<<<dim3(NCH, HH, BB), 256>>>(Ds);
    // 6) oln -> bf16 hi/lo
    ln_bf<DIN_><<<ROWS/8, 256>>>(p_yc, oln_w, oln_b, p_yh, p_yl);
    // 7) out = src + yln @ W_out
    hgemm<<<dim3(ROWS/128, 4), 256, HSMEM>>>(p_yh, p_yl, p_w3h, p_w3l, out, src,
                                             ROWS, DD, DIN_);
}

// round 17
// speedup vs baseline: 1.3352x; 1.0936x over previous
#include <cuda_runtime.h>
#include <cuda_fp16.h>
#include <math.h>
#include <stdint.h>

#define BB   8
#define LL   2048
#define DD   256
#define DIN_ 512
#define NN   64
#define PP   64
#define HH   8
#define ROWS (BB*LL)          // 16384
#define XPROJ (HH + 2*NN)     // 136
#define NCH  32
#define CT   64

typedef unsigned long long u64;

// ---------------- scratch (device globals) ---------------------------------
__device__ __half g_xh[ROWS*DD];                    // LN1 out (hi only)
__device__ float  g_ur [ROWS*DIN_];
__device__ __half g_uh[ROWS*DIN_], g_ul[ROWS*DIN_]; // gelu hi/lo (scan needs both)
__device__ float  g_dbc[ROWS*XPROJ];
__device__ float  g_yc [ROWS*DIN_];
__device__ __half g_yh[ROWS*DIN_];                  // oln out (hi only)
__device__ float  g_S  [BB*HH*NCH*NN*PP];
__device__ float  g_hin[BB*HH*NCH*NN*PP];
__device__ float  g_la [BB*HH*NCH*CT];
__device__ float  g_pa [BB*HH*NCH];
__device__ __half g_w1h[DIN_*DD],    g_w1l[DIN_*DD];
__device__ __half g_w2h[XPROJ*DIN_], g_w2l[XPROJ*DIN_];
__device__ __half g_w3h[DD*DIN_],    g_w3l[DD*DIN_];

// ---------------- helpers ---------------------------------------------------
__device__ __forceinline__ uint32_t smem_u32(const void* p){
    uint32_t a;
    asm("{ .reg .u64 t; cvta.to.shared.u64 t, %1; cvt.u32.u64 %0, t; }" : "=r"(a) : "l"(p));
    return a;
}
__device__ __forceinline__ void cp16(uint32_t dst, const void* src, int sz){
    asm volatile("cp.async.ca.shared.global [%0], [%1], 16, %2;"
                 :: "r"(dst), "l"(src), "r"(sz) : "memory");
}
#define CP_COMMIT() asm volatile("cp.async.commit_group;" ::: "memory")
#define CP_WAIT1()  asm volatile("cp.async.wait_group 1;" ::: "memory")
#define CP_WAIT0()  asm volatile("cp.async.wait_group 0;" ::: "memory")

#define LDSM4(r, a) asm volatile( \
    "ldmatrix.sync.aligned.m8n8.x4.shared.b16 {%0,%1,%2,%3}, [%4];" \
    : "=r"((r)[0]),"=r"((r)[1]),"=r"((r)[2]),"=r"((r)[3]) : "r"(a))

__device__ __forceinline__ void mma_f16(float* d, const uint32_t* a, const uint32_t* b){
    asm volatile("mma.sync.aligned.m16n8k16.row.col.f32.f16.f16.f32 "
        "{%0,%1,%2,%3}, {%4,%5,%6,%7}, {%8,%9}, {%0,%1,%2,%3};"
        : "+f"(d[0]), "+f"(d[1]), "+f"(d[2]), "+f"(d[3])
        : "r"(a[0]), "r"(a[1]), "r"(a[2]), "r"(a[3]), "r"(b[0]), "r"(b[1]));
}

// packed f32x2
#define PK2(d, lo, hi) asm("mov.b64 %0, {%1,%2};" : "=l"(d) : "r"(__float_as_uint(lo)), "r"(__float_as_uint(hi)))
#define DUP2(d, x)     asm("mov.b64 %0, {%1,%1};" : "=l"(d) : "r"(__float_as_uint(x)))
#define UPK2(lo, hi, v) do { uint32_t _a,_b; asm("mov.b64 {%0,%1}, %2;" : "=r"(_a), "=r"(_b) : "l"(v)); lo=__uint_as_float(_a); hi=__uint_as_float(_b); } while(0)
#define F2ACC(d, a, b) asm("fma.rn.f32x2 %0, %1, %2, %0;" : "+l"(d) : "l"(a), "l"(b))

__device__ __forceinline__ float4 ld4hl(const __half* hp, const __half* lp){
    uint2 vh = *(const uint2*)hp;
    uint2 vl = *(const uint2*)lp;
    float2 h0 = __half22float2(*(__half2*)&vh.x);
    float2 h1 = __half22float2(*(__half2*)&vh.y);
    float2 l0 = __half22float2(*(__half2*)&vl.x);
    float2 l1 = __half22float2(*(__half2*)&vl.y);
    return make_float4(h0.x + l0.x, h0.y + l0.y, h1.x + l1.x, h1.y + l1.y);
}

// ---------------- weight prep ------------------------------------------------
__global__ __launch_bounds__(256) void wprep(const float* __restrict__ W,
        __half* __restrict__ oh, __half* __restrict__ ol, int K, int N)
{
    int idx = blockIdx.x * 256 + threadIdx.x;
    if (idx >= K * N) return;
    int n = idx / K, k = idx - n * K;
    float v = W[(size_t)k * N + n];
    __half hh = __float2half(v);
    oh[idx] = hh;
    ol[idx] = __float2half(v - __half2float(hh));
}

// ---------------- LayerNorm -> fp16 hi (warp per row, vectorized) -----------
template<int W>
__global__ __launch_bounds__(256) void ln_h(const float* __restrict__ x,
        const float* __restrict__ w, const float* __restrict__ b,
        __half* __restrict__ yh)
{
    constexpr int E4 = W / 128;
    const int lane = threadIdx.x & 31;
    const int row  = blockIdx.x * 8 + (threadIdx.x >> 5);
    const float4* xr = (const float4*)(x + (size_t)row * W);
    float4 v[E4];
    float s = 0.f, q = 0.f;
#pragma unroll
    for (int i = 0; i < E4; i++) {
        v[i] = xr[lane + 32*i];
        s += v[i].x + v[i].y + v[i].z + v[i].w;
        q += v[i].x*v[i].x + v[i].y*v[i].y + v[i].z*v[i].z + v[i].w*v[i].w;
    }
#pragma unroll
    for (int o = 16; o; o >>= 1) {
        s += __shfl_xor_sync(0xffffffffu, s, o);
        q += __shfl_xor_sync(0xffffffffu, q, o);
    }
    float mean = s / (float)W;
    float rstd = rsqrtf(q / (float)W - mean*mean + 1e-5f);
    const float4* w4 = (const float4*)w;
    const float4* b4 = (const float4*)b;
#pragma unroll
    for (int i = 0; i < E4; i++) {
        int c4 = lane + 32*i;
        float4 wv = w4[c4], bv = b4[c4];
        __half hh[4];
        hh[0] = __float2half((v[i].x - mean)*rstd*wv.x + bv.x);
        hh[1] = __float2half((v[i].y - mean)*rstd*wv.y + bv.y);
        hh[2] = __float2half((v[i].z - mean)*rstd*wv.z + bv.z);
        hh[3] = __float2half((v[i].w - mean)*rstd*wv.w + bv.w);
        *(uint2*)(yh + (size_t)row*W + c4*4) = *(uint2*)hh;
    }
}

// ---------------- HMMA fp16 2-term GEMM, BM128 x BN64 -----------------------
// C = Ah@Bh^T + Ah@Bl^T (+addend) = Ah @ B (weights exact).
// Stage: Ah(10240) Bh(5120) Bl(5120) = 20480 B; 2 stages = 40960 B.
#define HA_OFF  0
#define HBH_OFF 10240
#define HBL_OFF 15360
#define HSTG    20480
#define HSMEM   40960
__global__ __launch_bounds__(256,2) void hgemm(
    const __half* __restrict__ Ah,
    const __half* __restrict__ Bh, const __half* __restrict__ Bl,
    float* __restrict__ C, const float* __restrict__ addend,
    int M, int N, int K)
{
    extern __shared__ char hsm[];
    const uint32_t sb = smem_u32(hsm);
    const int tid = threadIdx.x, wid = tid >> 5, lane = tid & 31;
    const int m0 = blockIdx.x * 128, n0 = blockIdx.y * 64;
    const int wm = (wid >> 1) * 32, wn = (wid & 1) * 32;
    const int NC = K >> 5;

    float acc[2][4][4];
#pragma unroll
    for (int i = 0; i < 2; i++)
#pragma unroll
        for (int j = 0; j < 4; j++)
#pragma unroll
            for (int q = 0; q < 4; q++) acc[i][j][q] = 0.f;

    auto issue = [&](int c){
        int s = c & 1;
        int k0 = c << 5;
        uint32_t stg = sb + s * HSTG;
#pragma unroll
        for (int i = 0; i < 4; i++) {
            int idx = tid + i * 256;
            if (idx < 512) {                  // A: 512 chunks of 16B
                int row = idx >> 2, cc = idx & 3;
                cp16(stg + HA_OFF + row*80 + cc*16,
                     Ah + (size_t)(m0 + row) * K + k0 + cc*8, 16);
            } else {                          // B hi/lo: 256 chunks each
                int j = idx - 512;
                int mat = j >> 8, w = j & 255, row = w >> 2, cc = w & 3;
                uint32_t dst = stg + (mat ? HBL_OFF : HBH_OFF) + row*80 + cc*16;
                int n = n0 + row;
                int ok = (n < N);
                const __half* Bp = mat ? Bl : Bh;
                cp16(dst, Bp + (size_t)(ok ? n : 0) * K + k0 + cc*8, ok ? 16 : 0);
            }
        }
    };

    const int rA  = wm + (lane & 15);
    const int kAo = (lane >> 4) * 16;
    const int rB  = wn + (lane & 7) + ((lane >> 4) & 1) * 8;
    const int kBo = ((lane >> 3) & 1) * 16;

    issue(0); CP_COMMIT();

    for (int c = 0; c < NC; c++) {
        int s = c & 1;
        if (c + 1 < NC) { issue(c + 1); CP_COMMIT(); CP_WAIT1(); }
        else            { CP_WAIT0(); }
        __syncthreads();
        uint32_t st = sb + s * HSTG;
#pragma unroll
        for (int ks = 0; ks < 2; ks++) {
            int ksb = ks * 32;
            uint32_t ah[2][4];
            uint32_t aAdr = st + HA_OFF + rA*80 + ksb + kAo;
            LDSM4(ah[0], aAdr);
            LDSM4(ah[1], aAdr + 16*80);
            uint32_t bh[4][2], bl[4][2];
            {
                uint32_t r4[4];
                uint32_t bAdr = st + HBH_OFF + rB*80 + ksb + kBo;
                LDSM4(r4, bAdr);
                bh[0][0]=r4[0]; bh[0][1]=r4[1]; bh[1][0]=r4[2]; bh[1][1]=r4[3];
                LDSM4(r4, bAdr + 16*80);
                bh[2][0]=r4[0]; bh[2][1]=r4[1]; bh[3][0]=r4[2]; bh[3][1]=r4[3];
                LDSM4(r4, bAdr + (HBL_OFF - HBH_OFF));
                bl[0][0]=r4[0]; bl[0][1]=r4[1]; bl[1][0]=r4[2]; bl[1][1]=r4[3];
                LDSM4(r4, bAdr + (HBL_OFF - HBH_OFF) + 16*80);
                bl[2][0]=r4[0]; bl[2][1]=r4[1]; bl[3][0]=r4[2]; bl[3][1]=r4[3];
            }
#pragma unroll
            for (int i = 0; i < 2; i++)
#pragma unroll
                for (int j = 0; j < 4; j++) {
                    mma_f16(acc[i][j], ah[i], bh[j]);
                    mma_f16(acc[i][j], ah[i], bl[j]);
                }
        }
        __syncthreads();
    }

    const int g = lane >> 2, tg = lane & 3;
#pragma unroll
    for (int i = 0; i < 2; i++) {
#pragma unroll
        for (int j = 0; j < 4; j++) {
            int col = n0 + wn + j*8 + tg*2;
            if (col >= N) continue;
            int mA = m0 + wm + i*16 + g;
            int mB = mA + 8;
            float2 v0 = make_float2(acc[i][j][0], acc[i][j][1]);
            float2 v1 = make_float2(acc[i][j][2], acc[i][j][3]);
            if (addend) {
                float2 a0 = *(const float2*)(addend + (size_t)mA * N + col);
                float2 a1 = *(const float2*)(addend + (size_t)mB * N + col);
                v0.x += a0.x; v0.y += a0.y; v1.x += a1.x; v1.y += a1.y;
            }
            *(float2*)(C + (size_t)mA * N + col) = v0;
            *(float2*)(C + (size_t)mB * N + col) = v1;
        }
    }
}

// ---------------- skinny GEMM: dbc cols 128..135 ----------------------------
__global__ __launch_bounds__(256) void skinny8(const float* __restrict__ Wx)
{
    __shared__ float sW[512*9];
    const int tid = threadIdx.x;
#pragma unroll
    for (int t = 0; t < 16; t++) {
        int idx = tid + t * 256;
        int k = idx >> 3, c = idx & 7;
        sW[k*9 + c] = Wx[(size_t)k * XPROJ + 128 + c];
    }
    __syncthreads();
    int row = blockIdx.x * 8 + (tid >> 5);
    int lane = tid & 31;
    float acc[8];
#pragma unroll
    for (int c = 0; c < 8; c++) acc[c] = 0.f;
    const __half* uh = g_uh + (size_t)row * DIN_;
    const __half* ul = g_ul + (size_t)row * DIN_;
#pragma unroll
    for (int i = 0; i < 4; i++) {
        int k = (lane + i * 32) * 4;
        float4 uv = ld4hl(uh + k, ul + k);
        float u4[4] = {uv.x, uv.y, uv.z, uv.w};
#pragma unroll
        for (int q = 0; q < 4; q++)
#pragma unroll
            for (int c = 0; c < 8; c++)
                acc[c] = fmaf(u4[q], sW[(k+q)*9 + c], acc[c]);
    }
#pragma unroll
    for (int o = 16; o; o >>= 1)
#pragma unroll
        for (int c = 0; c < 8; c++)
            acc[c] += __shfl_xor_sync(0xffffffffu, acc[c], o);
    if (lane == 0) {
#pragma unroll
        for (int c = 0; c < 8; c++)
            g_dbc[(size_t)row * XPROJ + 128 + c] = acc[c];
    }
}

// ---------------- depthwise conv3 + GELU -> fp16 hi/lo ----------------------
__global__ __launch_bounds__(256) void convgelu_k(const float* __restrict__ cw,
                                                  const float* __restrict__ cb)
{
    int idx = blockIdx.x * 256 + threadIdx.x;       // over ROWS*DIN_/4
    if (idx >= ROWS * DIN_ / 4) return;
    int cg = idx & 127;
    int l  = (idx >> 7) & (LL - 1);
    float4 mid = *(const float4*)(g_ur + (size_t)idx*4);
    float4 lft = make_float4(0,0,0,0), rgt = make_float4(0,0,0,0);
    if (l > 0)      lft = *(const float4*)(g_ur + (size_t)(idx - 128)*4);
    if (l < LL - 1) rgt = *(const float4*)(g_ur + (size_t)(idx + 128)*4);
    float m[4] = {mid.x, mid.y, mid.z, mid.w};
    float a[4] = {lft.x, lft.y, lft.z, lft.w};
    float r[4] = {rgt.x, rgt.y, rgt.z, rgt.w};
    __half oh[4], ol[4];
#pragma unroll
    for (int q = 0; q < 4; q++) {
        int c = cg * 4 + q;
        float x = a[q]*cw[c*3] + m[q]*cw[c*3+1] + r[q]*cw[c*3+2] + cb[c];
        float g = 0.5f * x * (1.f + erff(x * 0.7071067811865476f));
        oh[q] = __float2half(g);
        ol[q] = __float2half(g - __half2float(oh[q]));
    }
    *(uint2*)(g_uh + (size_t)idx*4) = *(uint2*)oh;
    *(uint2*)(g_ul + (size_t)idx*4) = *(uint2*)ol;
}

// ---------------- SSD phase A ------------------------------------------------
__global__ __launch_bounds__(256,2) void ssdA(const float* __restrict__ dt_bias,
                                              const float* __restrict__ A_log)
{
    extern __shared__ float sm[];
    float* sB  = sm;            // 64 x 65
    float* sC  = sm + 4160;
    float* sX  = sm + 8320;
    float* sP  = sm + 12480;
    float* sdt = sm + 16640;
    float* sla = sdt + 64;
    float* sw  = sla + 64;
    const int c = blockIdx.x, h = blockIdx.y, b = blockIdx.z;
    const int tid = threadIdx.x;
    const int tx = tid & 15, ty = tid >> 4;
    const size_t r0 = (size_t)b * LL + c * CT;
    const int bh = b * HH + h;

#pragma unroll
    for (int i = 0; i < 4; i++) {
        int row = i * 16 + ty;
        const float* dr = g_dbc + (r0 + row) * XPROJ;
        float4 bv = *(const float4*)(dr + 8  + tx*4);
        float4 cv = *(const float4*)(dr + 72 + tx*4);
        size_t uoff = (r0 + row)*DIN_ + h*64 + tx*4;
        float4 xv = ld4hl(g_uh + uoff, g_ul + uoff);
        sB[row*65 + tx*4+0]=bv.x; sB[row*65 + tx*4+1]=bv.y;
        sB[row*65 + tx*4+2]=bv.z; sB[row*65 + tx*4+3]=bv.w;
        sC[row*65 + tx*4+0]=cv.x; sC[row*65 + tx*4+1]=cv.y;
        sC[row*65 + tx*4+2]=cv.z; sC[row*65 + tx*4+3]=cv.w;
        sX[row*65 + tx*4+0]=xv.x; sX[row*65 + tx*4+1]=xv.y;
        sX[row*65 + tx*4+2]=xv.z; sX[row*65 + tx*4+3]=xv.w;
    }
    if (tid < 64) {
        float xx = g_dbc[(r0 + tid)*XPROJ + h] + dt_bias[h];
        float dt = (xx > 20.f) ? xx : log1pf(expf(xx));
        float la = -dt * expf(A_log[h]);
        int lane = tid & 31;
        float v = la;
#pragma unroll
        for (int o = 1; o < 32; o <<= 1) {
            float pv = __shfl_up_sync(0xffffffffu, v, o);
            if (lane >= o) v += pv;
        }
        sdt[tid] = dt;
        sla[tid] = v;
    }
    __syncthreads();
    if (tid >= 32 && tid < 64) sla[tid] += sla[31];
    __syncthreads();
    if (tid < 64) sw[tid] = sdt[tid] * __expf(sla[63] - sla[tid]);
    __syncthreads();

    u64 acc2[4][2];
#pragma unroll
    for (int i=0;i<4;i++) { acc2[i][0]=0ull; acc2[i][1]=0ull; }
#pragma unroll 8
    for (int n = 0; n < 64; n++) {
        u64 a2[4], b2[2];
#pragma unroll
        for (int i=0;i<4;i++) DUP2(a2[i], sC[(ty*4+i)*65 + n]);
        PK2(b2[0], sB[(tx*4+0)*65 + n], sB[(tx*4+1)*65 + n]);
        PK2(b2[1], sB[(tx*4+2)*65 + n], sB[(tx*4+3)*65 + n]);
#pragma unroll
        for (int i=0;i<4;i++) {
            F2ACC(acc2[i][0], a2[i], b2[0]);
            F2ACC(acc2[i][1], a2[i], b2[1]);
        }
    }
#pragma unroll
    for (int i=0;i<4;i++) {
        int t = ty*4 + i;
        float pv[4];
        UPK2(pv[0], pv[1], acc2[i][0]);
        UPK2(pv[2], pv[3], acc2[i][1]);
#pragma unroll
        for (int j=0;j<4;j++) {
            int s = tx*4 + j;
            sP[t*65 + s] = (s <= t) ? pv[j] * __expf(sla[t] - sla[s]) * sdt[s] : 0.f;
        }
    }
    __syncthreads();

#pragma unroll
    for (int i=0;i<4;i++) { acc2[i][0]=0ull; acc2[i][1]=0ull; }
#pragma unroll 8
    for (int s = 0; s < 64; s++) {
        u64 a2[4], b2[2];
#pragma unroll
        for (int i=0;i<4;i++) DUP2(a2[i], sP[(ty*4+i)*65 + s]);
        PK2(b2[0], sX[s*65 + tx*4+0], sX[s*65 + tx*4+1]);
        PK2(b2[1], sX[s*65 + tx*4+2], sX[s*65 + tx*4+3]);
#pragma unroll
        for (int i=0;i<4;i++) {
            F2ACC(acc2[i][0], a2[i], b2[0]);
            F2ACC(acc2[i][1], a2[i], b2[1]);
        }
    }
#pragma unroll
    for (int i=0;i<4;i++) {
        int t = ty*4 + i;
        float4 y;
        UPK2(y.x, y.y, acc2[i][0]);
        UPK2(y.z, y.w, acc2[i][1]);
        *(float4*)(g_yc + (r0 + t)*DIN_ + h*64 + tx*4) = y;
    }
    __syncthreads();

#pragma unroll
    for (int i = 0; i < 4; i++) {
        int row = i * 16 + ty;
        float wv = sw[row];
#pragma unroll
        for (int j = 0; j < 4; j++)
            sP[row*65 + tx*4 + j] = wv * sX[row*65 + tx*4 + j];
    }
    __syncthreads();

#pragma unroll
    for (int i=0;i<4;i++) { acc2[i][0]=0ull; acc2[i][1]=0ull; }
#pragma unroll 8
    for (int s = 0; s < 64; s++) {
        u64 a2[4], b2[2];
#pragma unroll
        for (int i=0;i<4;i++) DUP2(a2[i], sB[s*65 + ty*4 + i]);
        PK2(b2[0], sP[s*65 + tx*4+0], sP[s*65 + tx*4+1]);
        PK2(b2[1], sP[s*65 + tx*4+2], sP[s*65 + tx*4+3]);
#pragma unroll
        for (int i=0;i<4;i++) {
            F2ACC(acc2[i][0], a2[i], b2[0]);
            F2ACC(acc2[i][1], a2[i], b2[1]);
        }
    }
    size_t so = ((size_t)bh * NCH + c) * (NN*PP);
#pragma unroll
    for (int i=0;i<4;i++) {
        int n = ty*4 + i;
        float4 v;
        UPK2(v.x, v.y, acc2[i][0]);
        UPK2(v.z, v.w, acc2[i][1]);
        *(float4*)(g_S + so + n*64 + tx*4) = v;
    }
    if (tid < 64) g_la[((size_t)bh*NCH + c)*CT + tid] = sla[tid];
    if (tid == 0) g_pa[bh*NCH + c] = __expf(sla[63]);
}

// ---------------- SSD phase B (float4) ---------------------------------------
__global__ __launch_bounds__(256) void ssdB()
{
    int bh = blockIdx.x, tid = threadIdx.x;
    float4 h[4];
#pragma unroll
    for (int i=0;i<4;i++) h[i] = make_float4(0,0,0,0);
    const float4* S4 = (const float4*)g_S;
    float4* H4 = (float4*)g_hin;
    size_t base = (size_t)bh * NCH * (NN*PP/4);
    for (int c = 0; c < NCH; c++) {
        float pa = g_pa[bh*NCH + c];
        size_t cb = base + (size_t)c * (NN*PP/4);
#pragma unroll
        for (int i=0;i<4;i++) {
            size_t idx = cb + i*256 + tid;
            H4[idx] = h[i];
            float4 sv = S4[idx];
            h[i].x = h[i].x*pa + sv.x;
            h[i].y = h[i].y*pa + sv.y;
            h[i].z = h[i].z*pa + sv.z;
            h[i].w = h[i].w*pa + sv.w;
        }
    }
}

// ---------------- SSD phase C ------------------------------------------------
__global__ __launch_bounds__(256,2) void ssdC(const float* __restrict__ Ds)
{
    __shared__ float sCl[64*65];
    __shared__ float sH [64*65];
    __shared__ float sla2[64];
    const int c = blockIdx.x, h = blockIdx.y, b = blockIdx.z;
    const int tid = threadIdx.x;
    const int tx = tid & 15, ty = tid >> 4;
    const size_t r0 = (size_t)b * LL + c * CT;
    const int bh = b * HH + h;

    if (tid < 64) sla2[tid] = g_la[((size_t)bh*NCH + c)*CT + tid];
    __syncthreads();
#pragma unroll
    for (int i = 0; i < 4; i++) {
        int row = i * 16 + ty;
        float4 cv = *(const float4*)(g_dbc + (r0 + row)*XPROJ + 72 + tx*4);
        float e = __expf(sla2[row]);
        float4 hv = *(const float4*)(g_hin + ((size_t)bh*NCH + c)*(NN*PP) + row*64 + tx*4);
        sCl[row*65 + tx*4+0] = cv.x*e; sCl[row*65 + tx*4+1] = cv.y*e;
        sCl[row*65 + tx*4+2] = cv.z*e; sCl[row*65 + tx*4+3] = cv.w*e;
        sH [row*65 + tx*4+0] = hv.x;   sH [row*65 + tx*4+1] = hv.y;
        sH [row*65 + tx*4+2] = hv.z;   sH [row*65 + tx*4+3] = hv.w;
    }
    __syncthreads();

    u64 acc2[4][2];
#pragma unroll
    for (int i=0;i<4;i++) { acc2[i][0]=0ull; acc2[i][1]=0ull; }
#pragma unroll 8
    for (int n = 0; n < 64; n++) {
        u64 a2[4], b2[2];
#pragma unroll
        for (int i=0;i<4;i++) DUP2(a2[i], sCl[(ty*4+i)*65 + n]);
        PK2(b2[0], sH[n*65 + tx*4+0], sH[n*65 + tx*4+1]);
        PK2(b2[1], sH[n*65 + tx*4+2], sH[n*65 + tx*4+3]);
#pragma unroll
        for (int i=0;i<4;i++) {
            F2ACC(acc2[i][0], a2[i], b2[0]);
            F2ACC(acc2[i][1], a2[i], b2[1]);
        }
    }
    float dsh = Ds[h];
#pragma unroll
    for (int i=0;i<4;i++) {
        int t = ty*4 + i;
        float* yp = g_yc + (r0 + t)*DIN_ + h*64 + tx*4;
        float4 y1 = *(float4*)yp;
        size_t uoff = (r0 + t)*DIN_ + h*64 + tx*4;
        float4 xv = ld4hl(g_uh + uoff, g_ul + uoff);
        float a0,a1,a2v,a3;
        UPK2(a0, a1, acc2[i][0]);
        UPK2(a2v, a3, acc2[i][1]);
        y1.x += a0 + dsh*xv.x;
        y1.y += a1 + dsh*xv.y;
        y1.z += a2v + dsh*xv.z;
        y1.w += a3 + dsh*xv.w;
        *(float4*)yp = y1;
    }
}

// ---------------- launch ----------------------------------------------------
extern "C" void kernel_launch(void* const* d_in, const int* in_sizes, int n_in,
                              void* d_out, int out_size)
{
    const float* src     = (const float*)d_in[0];
    const float* ln_w    = (const float*)d_in[1];
    const float* ln_b    = (const float*)d_in[2];
    const float* W_in    = (const float*)d_in[3];
    const float* conv_w  = (const float*)d_in[4];
    const float* conv_b  = (const float*)d_in[5];
    const float* W_xproj = (const float*)d_in[6];
    const float* dt_bias = (const float*)d_in[7];
    const float* A_log   = (const float*)d_in[8];
    const float* Ds      = (const float*)d_in[9];
    const float* oln_w   = (const float*)d_in[10];
    const float* oln_b   = (const float*)d_in[11];
    const float* W_out   = (const float*)d_in[12];
    float* out = (float*)d_out;

    __half *p_xh,*p_uh,*p_ul,*p_yh;
    __half *p_w1h,*p_w1l,*p_w2h,*p_w2l,*p_w3h,*p_w3l;
    float *p_ur,*p_dbc,*p_yc;
    cudaGetSymbolAddress((void**)&p_xh, g_xh);
    cudaGetSymbolAddress((void**)&p_uh, g_uh);   cudaGetSymbolAddress((void**)&p_ul, g_ul);
    cudaGetSymbolAddress((void**)&p_yh, g_yh);
    cudaGetSymbolAddress((void**)&p_w1h, g_w1h); cudaGetSymbolAddress((void**)&p_w1l, g_w1l);
    cudaGetSymbolAddress((void**)&p_w2h, g_w2h); cudaGetSymbolAddress((void**)&p_w2l, g_w2l);
    cudaGetSymbolAddress((void**)&p_w3h, g_w3h); cudaGetSymbolAddress((void**)&p_w3l, g_w3l);
    cudaGetSymbolAddress((void**)&p_ur, g_ur);
    cudaGetSymbolAddress((void**)&p_dbc, g_dbc);
    cudaGetSymbolAddress((void**)&p_yc, g_yc);

    const int ASMEM = 67328;
    cudaFuncSetAttribute(ssdA, cudaFuncAttributeMaxDynamicSharedMemorySize, ASMEM);
    cudaFuncSetAttribute(hgemm, cudaFuncAttributeMaxDynamicSharedMemorySize, HSMEM);

    wprep<<<(DD*DIN_ + 255)/256, 256>>>(W_in,    p_w1h, p_w1l, DD,   DIN_);
    wprep<<<(DIN_*XPROJ + 255)/256, 256>>>(W_xproj, p_w2h, p_w2l, DIN_, XPROJ);
    wprep<<<(DIN_*DD + 255)/256, 256>>>(W_out,   p_w3h, p_w3l, DIN_, DD);

    // 1) LN1 -> fp16 hi
    ln_h<DD><<<ROWS/8, 256>>>(src, ln_w, ln_b, p_xh);
    // 2) ur = x @ W_in
    hgemm<<<dim3(ROWS/128, 8), 256, HSMEM>>>(p_xh, p_w1h, p_w1l, p_ur, nullptr,
                                             ROWS, DIN_, DD);
    // 3) u = gelu(conv3(ur)+b) -> fp16 hi/lo
    convgelu_k<<<(ROWS*DIN_/4 + 255)/256, 256>>>(conv_w, conv_b);
    // 4) dbc = u @ W_xproj
    hgemm<<<dim3(ROWS/128, 2), 256, HSMEM>>>(p_uh, p_w2h, p_w2l, p_dbc, nullptr,
                                             ROWS, XPROJ, DIN_);
    skinny8<<<ROWS/8, 256>>>(W_xproj);
    // 5) chunked scan
    ssdA<<<dim3(NCH, HH, BB), 256, ASMEM>>>(dt_bias, A_log);
    ssdB<<<BB*HH, 256>>>();
    ssdC<<<dim3(NCH, HH, BB), 256>>>(Ds);
    // 6) oln -> fp16 hi
    ln_h<DIN_><<<ROWS/8, 256>>>(p_yc, oln_w, oln_b, p_yh);
    // 7) out = src + yln @ W_out
    hgemm<<<dim3(ROWS/128, 4), 256, HSMEM>>>(p_yh, p_w3h, p_w3l, out, src,
                                             ROWS, DD, DIN_);
}